// round 6
// baseline (speedup 1.0000x reference)
#include <cuda_runtime.h>
#include <math.h>

#define CC 48
#define TT 400
#define FF 129
#define BB 2
#define TFT 51600        // T*F
#define CTF 2476800      // C*T*F
#define BCTF 4953600     // B*C*T*F
#define OC 96
#define OUT_SZ 9907200   // B*OC*T*F

typedef unsigned long long u64;

// ---- packed f32x2 helpers (SASS FFMA2; only reachable via PTX) ----
__device__ __forceinline__ void ffma2(u64 &d, u64 a, u64 b) {
    asm("fma.rn.f32x2 %0, %1, %2, %0;" : "+l"(d) : "l"(a), "l"(b));
}
__device__ __forceinline__ u64 pack2(float v) {
    u64 r; asm("mov.b64 %0, {%1, %2};" : "=l"(r) : "f"(v), "f"(v)); return r;
}
__device__ __forceinline__ u64 mul2(u64 a, u64 b) {
    u64 r; asm("mul.rn.f32x2 %0, %1, %2;" : "=l"(r) : "l"(a), "l"(b)); return r;
}
__device__ __forceinline__ float2 unpack2(u64 v) {
    float2 f; asm("mov.b64 {%0, %1}, %2;" : "=f"(f.x), "=f"(f.y) : "l"(v)); return f;
}

// Scratch (allowed: __device__ globals, no allocation)
__device__ __align__(16) float g_Q[BCTF];
__device__ __align__(16) float g_K[BCTF];
__device__ __align__(16) float g_Kref[BCTF];
__device__ __align__(16) float g_ref[BCTF];

// ===========================================================================
// Kernel 1 (merged): z=0 -> Q = pw1(dw1(x_mic)), K = pw2(dw2(Q))
//                    z=1 -> K_ref = pw3(dw3(x_ref))
// FFMA2 inner loop; weights duplicated in smem so w-pairs load ready-packed.
// ===========================================================================
#define PW_P 128
#define PW_NB 404        // ceil(51600/128)
#define SMEM_PW ((2*(CC*2*CC) + 2*CC + 2*CC*PW_P)*4)   // 86,784 B

__global__ __launch_bounds__(384) void pw_kernel(
    const float* __restrict__ x_mic, const float* __restrict__ x_ref,
    const float* __restrict__ dw1w, const float* __restrict__ dw1b,
    const float* __restrict__ pw1w, const float* __restrict__ pw1b,
    const float* __restrict__ dw2w, const float* __restrict__ dw2b,
    const float* __restrict__ pw2w, const float* __restrict__ pw2b,
    const float* __restrict__ dw3w, const float* __restrict__ dw3b,
    const float* __restrict__ pw3w, const float* __restrict__ pw3b)
{
    extern __shared__ float smp[];
    float* W1d = smp;                      // CC x 2*CC (duplicated)
    float* W2d = W1d + CC*2*CC;
    float* bb1 = W2d + CC*2*CC;            // CC
    float* bb2 = bb1 + CC;                 // CC
    float* xs  = bb2 + CC;                 // CC*PW_P
    float* qs  = xs + CC*PW_P;             // CC*PW_P

    const int tid = threadIdx.x;
    const int b = blockIdx.y, job = blockIdx.z;
    const int p0 = blockIdx.x * PW_P;
    const float* x   = job ? x_ref : x_mic;
    const float* w1  = job ? pw3w : pw1w;
    const float* d1w = job ? dw3w : dw1w;
    const float* p1b = job ? pw3b : pw1b;
    const float* d1b = job ? dw3b : dw1b;

    for (int i = tid; i < CC*CC; i += 384) {
        int o = i / CC, c = i % CC;
        float v1 = w1[i] * d1w[c];
        W1d[c*(2*CC) + 2*o] = v1; W1d[c*(2*CC) + 2*o + 1] = v1;
        if (!job) {
            float v2 = pw2w[i] * dw2w[c];
            W2d[c*(2*CC) + 2*o] = v2; W2d[c*(2*CC) + 2*o + 1] = v2;
        }
    }
    if (tid < CC) {
        float s1 = p1b[tid];
        for (int c = 0; c < CC; c++) s1 += w1[tid*CC+c] * d1b[c];
        bb1[tid] = s1;
        if (!job) {
            float s2 = pw2b[tid];
            for (int c = 0; c < CC; c++) s2 += pw2w[tid*CC+c] * dw2b[c];
            bb2[tid] = s2;
        }
    }
    for (int i = tid; i < CC*PW_P; i += 384) {
        int c = i / PW_P, p = i % PW_P;
        int gp = p0 + p;
        xs[i] = (gp < TFT) ? x[(size_t)b*CTF + (size_t)c*TFT + gp] : 0.f;
    }
    __syncthreads();

    const int ot = tid >> 5, pt = tid & 31;   // 12 o-tiles x 32 p-tiles
    const int o0 = ot*4, pp = pt*4;
    const int gp0 = p0 + pp;
    float* out1 = job ? g_Kref : g_Q;

    // stage 1
    {
        u64 acc[4][2] = {};
        #pragma unroll 4
        for (int c = 0; c < CC; c++) {
            ulonglong2 wa = *(const ulonglong2*)&W1d[c*(2*CC) + 2*o0];
            ulonglong2 wb = *(const ulonglong2*)&W1d[c*(2*CC) + 2*o0 + 4];
            ulonglong2 xv = *(const ulonglong2*)&xs[c*PW_P + pp];
            ffma2(acc[0][0], wa.x, xv.x); ffma2(acc[0][1], wa.x, xv.y);
            ffma2(acc[1][0], wa.y, xv.x); ffma2(acc[1][1], wa.y, xv.y);
            ffma2(acc[2][0], wb.x, xv.x); ffma2(acc[2][1], wb.x, xv.y);
            ffma2(acc[3][0], wb.y, xv.x); ffma2(acc[3][1], wb.y, xv.y);
        }
        size_t base = (size_t)b*CTF + gp0;
        #pragma unroll
        for (int o = 0; o < 4; o++) {
            float bv = bb1[o0+o];
            float2 lo = unpack2(acc[o][0]), hi = unpack2(acc[o][1]);
            float4 r = make_float4(lo.x+bv, lo.y+bv, hi.x+bv, hi.y+bv);
            if (!job) *(float4*)&qs[(o0+o)*PW_P + pp] = r;
            if (gp0 < TFT) *(float4*)&out1[base + (size_t)(o0+o)*TFT] = r;
        }
    }
    if (job) return;
    __syncthreads();

    // stage 2: K from Q tile in smem
    {
        u64 acc[4][2] = {};
        #pragma unroll 4
        for (int c = 0; c < CC; c++) {
            ulonglong2 wa = *(const ulonglong2*)&W2d[c*(2*CC) + 2*o0];
            ulonglong2 wb = *(const ulonglong2*)&W2d[c*(2*CC) + 2*o0 + 4];
            ulonglong2 xv = *(const ulonglong2*)&qs[c*PW_P + pp];
            ffma2(acc[0][0], wa.x, xv.x); ffma2(acc[0][1], wa.x, xv.y);
            ffma2(acc[1][0], wa.y, xv.x); ffma2(acc[1][1], wa.y, xv.y);
            ffma2(acc[2][0], wb.x, xv.x); ffma2(acc[2][1], wb.x, xv.y);
            ffma2(acc[3][0], wb.y, xv.x); ffma2(acc[3][1], wb.y, xv.y);
        }
        if (gp0 < TFT) {
            size_t base = (size_t)b*CTF + gp0;
            #pragma unroll
            for (int o = 0; o < 4; o++) {
                float bv = bb2[o0+o];
                float2 lo = unpack2(acc[o][0]), hi = unpack2(acc[o][1]);
                *(float4*)&g_K[base + (size_t)(o0+o)*TFT] =
                    make_float4(lo.x+bv, lo.y+bv, hi.x+bv, hi.y+bv);
            }
        }
    }
}

// ===========================================================================
// Kernel 2: mic attention per (b,t), 512 threads, FFMA2 everywhere.
//   K duplicated in smem -> score k-operands load ready-packed.
//   softmax per f-column (no shuffles), 1/sum folded into AV epilogue.
// ===========================================================================
#define ATW 132          // A_T row stride (f)
#define KD  272          // duplicated K row width (2*136)
#define KSW 136          // padded g rows
#define XTW 52           // X_T row stride (c)
#define SMEM_ATTN ((CC*ATW + CC*KD + KSW*XTW + KSW*ATW + ATW)*4)  // 178,192 B

__global__ __launch_bounds__(512) void mic_attn_kernel(
    const float* __restrict__ x_mic, float* __restrict__ mic_out)
{
    extern __shared__ float sm[];
    float* Qs  = sm;                   // [CC][ATW]
    float* Ksd = Qs + CC*ATW;          // [CC][KD]   (K duplicated per g)
    float* XT  = Ksd + CC*KD;          // [KSW][XTW] (X transposed)
    float* AT  = XT + KSW*XTW;         // [KSW][ATW] (A transposed [g][f])
    float* SIv = AT + KSW*ATW;         // [ATW]

    const int tid = threadIdx.x;
    const int t = blockIdx.x, b = blockIdx.y;
    const size_t rbase = (size_t)b*CTF + (size_t)t*FF;

    for (int i = tid; i < CC*ATW; i += 512) {
        int c = i / ATW, f = i % ATW;
        Qs[i] = (f < FF) ? g_Q[rbase + (size_t)c*TFT + f] : 0.f;
    }
    for (int i = tid; i < CC*KD; i += 512) {
        int c = i / KD, gg = i % KD, g = gg >> 1;
        Ksd[i] = (g < FF) ? g_K[rbase + (size_t)c*TFT + g] : 0.f;
    }
    for (int i = tid; i < CC*KSW; i += 512) {
        int c = i / KSW, g = i % KSW;
        XT[g*XTW + c] = (g < FF) ? x_mic[rbase + (size_t)c*TFT + g] : 0.f;
    }
    __syncthreads();

    // ---- scores: 17 g-tiles(8) x 33 f-tiles(4) = 561 tiles ----
    for (int idx = tid; idx < 17*33; idx += 512) {
        int gt = idx / 33, ft = idx % 33;
        int g0 = gt*8, f0 = ft*4;
        u64 acc[8][2] = {};
        const float* krow = &Ksd[2*g0];
        #pragma unroll 2
        for (int c = 0; c < CC; c++) {
            ulonglong2 q   = *(const ulonglong2*)&Qs[c*ATW + f0];
            ulonglong2 k01 = *(const ulonglong2*)&krow[c*KD];
            ulonglong2 k23 = *(const ulonglong2*)&krow[c*KD + 4];
            ulonglong2 k45 = *(const ulonglong2*)&krow[c*KD + 8];
            ulonglong2 k67 = *(const ulonglong2*)&krow[c*KD + 12];
            ffma2(acc[0][0], k01.x, q.x); ffma2(acc[0][1], k01.x, q.y);
            ffma2(acc[1][0], k01.y, q.x); ffma2(acc[1][1], k01.y, q.y);
            ffma2(acc[2][0], k23.x, q.x); ffma2(acc[2][1], k23.x, q.y);
            ffma2(acc[3][0], k23.y, q.x); ffma2(acc[3][1], k23.y, q.y);
            ffma2(acc[4][0], k45.x, q.x); ffma2(acc[4][1], k45.x, q.y);
            ffma2(acc[5][0], k45.y, q.x); ffma2(acc[5][1], k45.y, q.y);
            ffma2(acc[6][0], k67.x, q.x); ffma2(acc[6][1], k67.x, q.y);
            ffma2(acc[7][0], k67.y, q.x); ffma2(acc[7][1], k67.y, q.y);
        }
        #pragma unroll
        for (int g = 0; g < 8; g++) {
            ulonglong2 st; st.x = acc[g][0]; st.y = acc[g][1];
            *(ulonglong2*)&AT[(g0+g)*ATW + f0] = st;
        }
    }
    __syncthreads();

    // ---- softmax over g per f-column; scores tiny -> no max shift ----
    if (tid < ATW) {
        const int f = tid;
        const float rs = 0.14433756729740643f;   // 1/sqrt(48)
        float a0=0.f, a1=0.f, a2=0.f, a3=0.f;
        for (int g = 0; g < 128; g += 4) {
            float e0 = __expf(AT[(g+0)*ATW+f]*rs);
            float e1 = __expf(AT[(g+1)*ATW+f]*rs);
            float e2 = __expf(AT[(g+2)*ATW+f]*rs);
            float e3 = __expf(AT[(g+3)*ATW+f]*rs);
            AT[(g+0)*ATW+f] = e0; AT[(g+1)*ATW+f] = e1;
            AT[(g+2)*ATW+f] = e2; AT[(g+3)*ATW+f] = e3;
            a0 += e0; a1 += e1; a2 += e2; a3 += e3;
        }
        float e = __expf(AT[128*ATW+f]*rs);
        AT[128*ATW+f] = e;
        SIv[f] = 1.f / (a0+a1+a2+a3+e);
    }
    __syncthreads();

    // ---- AV: 12 c-tiles(4) x 33 f-tiles(4) = 396 tiles ----
    for (int idx = tid; idx < 12*33; idx += 512) {
        int ct = idx / 33, ft = idx % 33;
        int c0 = ct*4, f0 = ft*4;
        u64 acc[4][2] = {};
        #pragma unroll 3
        for (int g = 0; g < FF; g++) {
            ulonglong2 a = *(const ulonglong2*)&AT[g*ATW + f0];
            float4 xv = *(const float4*)&XT[g*XTW + c0];   // broadcast
            u64 x0 = pack2(xv.x), x1 = pack2(xv.y), x2 = pack2(xv.z), x3 = pack2(xv.w);
            ffma2(acc[0][0], x0, a.x); ffma2(acc[0][1], x0, a.y);
            ffma2(acc[1][0], x1, a.x); ffma2(acc[1][1], x1, a.y);
            ffma2(acc[2][0], x2, a.x); ffma2(acc[2][1], x2, a.y);
            ffma2(acc[3][0], x3, a.x); ffma2(acc[3][1], x3, a.y);
        }
        ulonglong2 iv = *(const ulonglong2*)&SIv[f0];
        #pragma unroll
        for (int i = 0; i < 4; i++) {
            float2 lo = unpack2(mul2(acc[i][0], iv.x));
            float2 hi = unpack2(mul2(acc[i][1], iv.y));
            float v[4] = {lo.x, lo.y, hi.x, hi.y};
            size_t ob = rbase + (size_t)(c0+i)*TFT;
            #pragma unroll
            for (int j = 0; j < 4; j++) {
                int f = f0 + j;
                if (f < FF) mic_out[ob + f] = v[j];   // scalar: rbase not 16B-aligned
            }
        }
    }
}

// ===========================================================================
// Kernel 3: sliding-window ref attention; 16 t's/block, 512 threads.
// ===========================================================================
#define RFP 132
#define RT 16
#define RROWS (RT + 10)

__global__ __launch_bounds__(512) void ref_attn_kernel(const float* __restrict__ x_ref)
{
    __shared__ __align__(16) float krs[RROWS*RFP];
    __shared__ __align__(16) float xrs[RROWS*RFP];

    const int tid = threadIdx.x;
    const int t0 = blockIdx.x * RT;
    const int h = blockIdx.y, b = blockIdx.z;
    const size_t base = (size_t)b*CTF + (size_t)h*TFT;

    for (int i = tid; i < RROWS*RFP; i += 512) {
        int r = i / RFP, f = i % RFP;
        int tk = t0 - 10 + r;
        bool ok = (tk >= 0) && (f < FF);
        size_t gi = base + (size_t)tk*FF + f;
        krs[i] = ok ? g_Kref[gi] : 0.f;
        xrs[i] = ok ? x_ref[gi]  : 0.f;
    }
    __syncthreads();

    const int w = tid >> 5, lane = tid & 31;
    const int t = t0 + w;
    const size_t qbase = base + (size_t)t*FF;

    float qv[5], acc[5];
    bool val[5];
    #pragma unroll
    for (int k = 0; k < 5; k++) {
        int f = lane + 32*k;
        val[k] = f < FF;
        qv[k] = val[k] ? g_Q[qbase + f] : 0.f;
        acc[k] = 0.f;
    }

    for (int j = 0; j < 11; j++) {
        int tk = t - 10 + j;
        if (tk < 0) continue;
        int r = w + j;
        float e[5]; float s = 0.f;
        float xv[5];
        #pragma unroll
        for (int k = 0; k < 5; k++) {
            int f = lane + 32*k;
            float kv = val[k] ? krs[r*RFP+f] : 0.f;
            xv[k]    = val[k] ? xrs[r*RFP+f] : 0.f;
            e[k] = val[k] ? __expf(qv[k]*kv) : 0.f;
            s += e[k];
        }
        #pragma unroll
        for (int off = 16; off; off >>= 1) s += __shfl_xor_sync(0xffffffffu, s, off);
        float inv = 1.f/s;
        #pragma unroll
        for (int k = 0; k < 5; k++)
            acc[k] += xv[k] * (e[k]*inv);
    }
    #pragma unroll
    for (int k = 0; k < 5; k++) {
        int f = lane + 32*k;
        if (val[k]) g_ref[qbase + f] = acc[k];
    }
}

// ===========================================================================
// Kernel 4: fusion 96x96 GEMM + folded BN + PReLU.
// 768 threads (24 o-tiles x 32 p-tiles), FFMA2, 2 CTAs/SM.
// ===========================================================================
#define FUS_P 128
#define FUS_NB 404
#define SMEM_FUS ((OC*OC + 2*OC + OC*FUS_P)*4)   // 86,784 B

__global__ __launch_bounds__(768) void fusion_kernel(
    const float* __restrict__ fw, const float* __restrict__ fb,
    const float* __restrict__ gamma, const float* __restrict__ beta,
    const float* __restrict__ mean, const float* __restrict__ var,
    const float* __restrict__ prelu_a,
    const float* __restrict__ micp,
    float* __restrict__ outp)
{
    extern __shared__ float smf[];
    float* WT    = smf;             // OC*OC transposed, BN-folded
    float* bias  = WT + OC*OC;
    float* alpha = bias + OC;
    float* comb  = alpha + OC;      // OC*FUS_P

    const int tid = threadIdx.x;
    const int b  = blockIdx.y;
    const int p0 = blockIdx.x * FUS_P;

    if (tid < OC) {
        float a = gamma[tid] * rsqrtf(var[tid] + 1e-5f);
        alpha[tid] = a;
        bias[tid] = (fb[tid] - mean[tid]) * a + beta[tid];
    }
    __syncthreads();
    for (int i = tid; i < OC*OC; i += 768) {
        int o = i / OC, c = i % OC;
        WT[c*OC+o] = fw[i] * alpha[o];
    }
    for (int i = tid; i < OC*FUS_P; i += 768) {
        int c = i / FUS_P, p = i % FUS_P;
        int gp = p0 + p;
        float v = 0.f;
        if (gp < TFT) {
            if (c < CC) v = micp[(size_t)b*CTF + (size_t)c*TFT + gp];
            else        v = g_ref[(size_t)b*CTF + (size_t)(c-CC)*TFT + gp];
        }
        comb[i] = v;
    }
    __syncthreads();

    const float pa = prelu_a[0];
    const int ot = tid >> 5, pt = tid & 31;    // 24 o-tiles(4) x 32 p-tiles(4)
    const int o0 = ot*4, pp = pt*4;
    const int gp0 = p0 + pp;

    u64 acc[4][2] = {};
    #pragma unroll 4
    for (int c = 0; c < OC; c++) {
        float4 w = *(const float4*)&WT[c*OC + o0];           // broadcast
        ulonglong2 xv = *(const ulonglong2*)&comb[c*FUS_P + pp];
        u64 w0 = pack2(w.x), w1 = pack2(w.y), w2 = pack2(w.z), w3 = pack2(w.w);
        ffma2(acc[0][0], w0, xv.x); ffma2(acc[0][1], w0, xv.y);
        ffma2(acc[1][0], w1, xv.x); ffma2(acc[1][1], w1, xv.y);
        ffma2(acc[2][0], w2, xv.x); ffma2(acc[2][1], w2, xv.y);
        ffma2(acc[3][0], w3, xv.x); ffma2(acc[3][1], w3, xv.y);
    }
    if (gp0 < TFT) {
        size_t ob = (size_t)b*OC*TFT + gp0;
        #pragma unroll
        for (int o = 0; o < 4; o++) {
            float bs = bias[o0+o];
            float2 lo = unpack2(acc[o][0]), hi = unpack2(acc[o][1]);
            float4 y = make_float4(lo.x+bs, lo.y+bs, hi.x+bs, hi.y+bs);
            y.x = (y.x >= 0.f) ? y.x : pa*y.x;
            y.y = (y.y >= 0.f) ? y.y : pa*y.y;
            y.z = (y.z >= 0.f) ? y.z : pa*y.z;
            y.w = (y.w >= 0.f) ? y.w : pa*y.w;
            *(float4*)&outp[ob + (size_t)(o0+o)*TFT] = y;
        }
    }
}

// ---------------------------------------------------------------------------
extern "C" void kernel_launch(void* const* d_in, const int* in_sizes, int n_in,
                              void* d_out, int out_size)
{
    const float* x_mic = (const float*)d_in[0];
    const float* x_ref = (const float*)d_in[1];
    const float* dw1w = (const float*)d_in[2];
    const float* dw1b = (const float*)d_in[3];
    const float* pw1w = (const float*)d_in[4];
    const float* pw1b = (const float*)d_in[5];
    const float* dw2w = (const float*)d_in[6];
    const float* dw2b = (const float*)d_in[7];
    const float* pw2w = (const float*)d_in[8];
    const float* pw2b = (const float*)d_in[9];
    const float* dw3w = (const float*)d_in[10];
    const float* dw3b = (const float*)d_in[11];
    const float* pw3w = (const float*)d_in[12];
    const float* pw3b = (const float*)d_in[13];
    const float* fw   = (const float*)d_in[14];
    const float* fb   = (const float*)d_in[15];
    const float* gam  = (const float*)d_in[16];
    const float* bet  = (const float*)d_in[17];
    const float* mea  = (const float*)d_in[18];
    const float* var  = (const float*)d_in[19];
    const float* pa   = (const float*)d_in[20];

    float* outp = (float*)d_out;
    float* micp = outp + OUT_SZ;    // second tuple output region

    cudaFuncSetAttribute(pw_kernel,
                         cudaFuncAttributeMaxDynamicSharedMemorySize, SMEM_PW);
    cudaFuncSetAttribute(mic_attn_kernel,
                         cudaFuncAttributeMaxDynamicSharedMemorySize, SMEM_ATTN);
    cudaFuncSetAttribute(fusion_kernel,
                         cudaFuncAttributeMaxDynamicSharedMemorySize, SMEM_FUS);

    pw_kernel<<<dim3(PW_NB, BB, 2), 384, SMEM_PW>>>(
        x_mic, x_ref, dw1w, dw1b, pw1w, pw1b, dw2w, dw2b, pw2w, pw2b,
        dw3w, dw3b, pw3w, pw3b);
    mic_attn_kernel<<<dim3(TT, BB), 512, SMEM_ATTN>>>(x_mic, micp);
    ref_attn_kernel<<<dim3(TT/RT, CC, BB), 512>>>(x_ref);
    fusion_kernel<<<dim3(FUS_NB, BB), 768, SMEM_FUS>>>(
        fw, fb, gam, bet, mea, var, pa, micp, outp);
}

// round 7
// speedup vs baseline: 1.0469x; 1.0469x over previous
#include <cuda_runtime.h>
#include <math.h>

#define CC 48
#define TT 400
#define FF 129
#define BB 2
#define TFT 51600        // T*F
#define CTF 2476800      // C*T*F
#define BCTF 4953600     // B*C*T*F
#define OC 96
#define OUT_SZ 9907200   // B*OC*T*F

typedef unsigned long long u64;

// ---- packed f32x2 helpers (SASS FFMA2; only reachable via PTX) ----
__device__ __forceinline__ void ffma2(u64 &d, u64 a, u64 b) {
    asm("fma.rn.f32x2 %0, %1, %2, %0;" : "+l"(d) : "l"(a), "l"(b));
}
__device__ __forceinline__ u64 pack2(float v) {
    u64 r; asm("mov.b64 %0, {%1, %2};" : "=l"(r) : "f"(v), "f"(v)); return r;
}
__device__ __forceinline__ u64 mul2(u64 a, u64 b) {
    u64 r; asm("mul.rn.f32x2 %0, %1, %2;" : "=l"(r) : "l"(a), "l"(b)); return r;
}
__device__ __forceinline__ float2 unpack2(u64 v) {
    float2 f; asm("mov.b64 {%0, %1}, %2;" : "=f"(f.x), "=f"(f.y) : "l"(v)); return f;
}

// Scratch (allowed: __device__ globals, no allocation)
__device__ __align__(16) float g_Q[BCTF];
__device__ __align__(16) float g_K[BCTF];
__device__ __align__(16) float g_Kref[BCTF];
__device__ __align__(16) float g_ref[BCTF];

// ===========================================================================
// Kernel 1 (merged): z=0 -> Q = pw1(dw1(x_mic)), K = pw2(dw2(Q))
//                    z=1 -> K_ref = pw3(dw3(x_ref))
// FFMA2 with register-packed weights (no smem duplication): 68KB, 3 CTAs/SM.
// ===========================================================================
#define PW_P 128
#define PW_NB 404        // ceil(51600/128)
#define SMEM_PW ((2*CC*CC + 2*CC + 2*CC*PW_P)*4)   // 67,968 B

__global__ __launch_bounds__(384) void pw_kernel(
    const float* __restrict__ x_mic, const float* __restrict__ x_ref,
    const float* __restrict__ dw1w, const float* __restrict__ dw1b,
    const float* __restrict__ pw1w, const float* __restrict__ pw1b,
    const float* __restrict__ dw2w, const float* __restrict__ dw2b,
    const float* __restrict__ pw2w, const float* __restrict__ pw2b,
    const float* __restrict__ dw3w, const float* __restrict__ dw3b,
    const float* __restrict__ pw3w, const float* __restrict__ pw3b)
{
    extern __shared__ float smp[];
    float* W1T = smp;                  // CC*CC transposed
    float* W2T = W1T + CC*CC;
    float* bb1 = W2T + CC*CC;          // CC
    float* bb2 = bb1 + CC;             // CC
    float* xs  = bb2 + CC;             // CC*PW_P
    float* qs  = xs + CC*PW_P;         // CC*PW_P

    const int tid = threadIdx.x;
    const int b = blockIdx.y, job = blockIdx.z;
    const int p0 = blockIdx.x * PW_P;
    const float* x   = job ? x_ref : x_mic;
    const float* w1  = job ? pw3w : pw1w;
    const float* d1w = job ? dw3w : dw1w;
    const float* p1b = job ? pw3b : pw1b;
    const float* d1b = job ? dw3b : dw1b;

    for (int i = tid; i < CC*CC; i += 384) {
        int o = i / CC, c = i % CC;
        W1T[c*CC+o] = w1[i] * d1w[c];
        if (!job) W2T[c*CC+o] = pw2w[i] * dw2w[c];
    }
    if (tid < CC) {
        float s1 = p1b[tid];
        for (int c = 0; c < CC; c++) s1 += w1[tid*CC+c] * d1b[c];
        bb1[tid] = s1;
        if (!job) {
            float s2 = pw2b[tid];
            for (int c = 0; c < CC; c++) s2 += pw2w[tid*CC+c] * dw2b[c];
            bb2[tid] = s2;
        }
    }
    for (int i = tid; i < CC*PW_P; i += 384) {
        int c = i / PW_P, p = i % PW_P;
        int gp = p0 + p;
        xs[i] = (gp < TFT) ? x[(size_t)b*CTF + (size_t)c*TFT + gp] : 0.f;
    }
    __syncthreads();

    const int ot = tid >> 5, pt = tid & 31;   // 12 o-tiles x 32 p-tiles
    const int o0 = ot*4, pp = pt*4;
    const int gp0 = p0 + pp;
    float* out1 = job ? g_Kref : g_Q;

    // stage 1
    {
        u64 acc[4][2] = {};
        #pragma unroll 4
        for (int c = 0; c < CC; c++) {
            float4 w = *(const float4*)&W1T[c*CC + o0];        // broadcast
            ulonglong2 xv = *(const ulonglong2*)&xs[c*PW_P + pp];
            u64 w0 = pack2(w.x), w1r = pack2(w.y), w2 = pack2(w.z), w3 = pack2(w.w);
            ffma2(acc[0][0], w0, xv.x);  ffma2(acc[0][1], w0, xv.y);
            ffma2(acc[1][0], w1r, xv.x); ffma2(acc[1][1], w1r, xv.y);
            ffma2(acc[2][0], w2, xv.x);  ffma2(acc[2][1], w2, xv.y);
            ffma2(acc[3][0], w3, xv.x);  ffma2(acc[3][1], w3, xv.y);
        }
        size_t base = (size_t)b*CTF + gp0;
        #pragma unroll
        for (int o = 0; o < 4; o++) {
            float bv = bb1[o0+o];
            float2 lo = unpack2(acc[o][0]), hi = unpack2(acc[o][1]);
            float4 r = make_float4(lo.x+bv, lo.y+bv, hi.x+bv, hi.y+bv);
            if (!job) *(float4*)&qs[(o0+o)*PW_P + pp] = r;
            if (gp0 < TFT) *(float4*)&out1[base + (size_t)(o0+o)*TFT] = r;
        }
    }
    if (job) return;
    __syncthreads();

    // stage 2: K from Q tile in smem
    {
        u64 acc[4][2] = {};
        #pragma unroll 4
        for (int c = 0; c < CC; c++) {
            float4 w = *(const float4*)&W2T[c*CC + o0];        // broadcast
            ulonglong2 xv = *(const ulonglong2*)&qs[c*PW_P + pp];
            u64 w0 = pack2(w.x), w1r = pack2(w.y), w2 = pack2(w.z), w3 = pack2(w.w);
            ffma2(acc[0][0], w0, xv.x);  ffma2(acc[0][1], w0, xv.y);
            ffma2(acc[1][0], w1r, xv.x); ffma2(acc[1][1], w1r, xv.y);
            ffma2(acc[2][0], w2, xv.x);  ffma2(acc[2][1], w2, xv.y);
            ffma2(acc[3][0], w3, xv.x);  ffma2(acc[3][1], w3, xv.y);
        }
        if (gp0 < TFT) {
            size_t base = (size_t)b*CTF + gp0;
            #pragma unroll
            for (int o = 0; o < 4; o++) {
                float bv = bb2[o0+o];
                float2 lo = unpack2(acc[o][0]), hi = unpack2(acc[o][1]);
                *(float4*)&g_K[base + (size_t)(o0+o)*TFT] =
                    make_float4(lo.x+bv, lo.y+bv, hi.x+bv, hi.y+bv);
            }
        }
    }
}

// ===========================================================================
// Kernel 2: mic attention per (b,t), 512 threads, FFMA2 with register-packed
// K (no smem duplication -> R5-level LDS traffic, half the fma slots).
// ===========================================================================
#define ATW 132          // A_T row stride (f)
#define KSW 136          // K row stride / padded g rows
#define XTW 52           // X_T row stride (c)
#define SMEM_ATTN ((CC*ATW + CC*KSW + KSW*XTW + KSW*ATW + ATW)*4)  // 152,080 B

__global__ __launch_bounds__(512) void mic_attn_kernel(
    const float* __restrict__ x_mic, float* __restrict__ mic_out)
{
    extern __shared__ float sm[];
    float* Qs  = sm;                   // [CC][ATW]
    float* Ks  = Qs + CC*ATW;          // [CC][KSW]
    float* XT  = Ks + CC*KSW;          // [KSW][XTW] (X transposed)
    float* AT  = XT + KSW*XTW;         // [KSW][ATW] (A transposed [g][f])
    float* SIv = AT + KSW*ATW;         // [ATW]

    const int tid = threadIdx.x;
    const int t = blockIdx.x, b = blockIdx.y;
    const size_t rbase = (size_t)b*CTF + (size_t)t*FF;

    for (int i = tid; i < CC*ATW; i += 512) {
        int c = i / ATW, f = i % ATW;
        Qs[i] = (f < FF) ? g_Q[rbase + (size_t)c*TFT + f] : 0.f;
    }
    for (int i = tid; i < CC*KSW; i += 512) {
        int c = i / KSW, g = i % KSW;
        Ks[i] = (g < FF) ? g_K[rbase + (size_t)c*TFT + g] : 0.f;
    }
    for (int i = tid; i < CC*KSW; i += 512) {
        int c = i / KSW, g = i % KSW;
        XT[g*XTW + c] = (g < FF) ? x_mic[rbase + (size_t)c*TFT + g] : 0.f;
    }
    __syncthreads();

    // ---- scores: 17 g-tiles(8) x 33 f-tiles(4) = 561 tiles ----
    for (int idx = tid; idx < 17*33; idx += 512) {
        int gt = idx / 33, ft = idx % 33;
        int g0 = gt*8, f0 = ft*4;
        u64 acc[8][2] = {};
        #pragma unroll 2
        for (int c = 0; c < CC; c++) {
            ulonglong2 q = *(const ulonglong2*)&Qs[c*ATW + f0];
            float4 ka = *(const float4*)&Ks[c*KSW + g0];
            float4 kb = *(const float4*)&Ks[c*KSW + g0 + 4];
            u64 k0 = pack2(ka.x), k1 = pack2(ka.y), k2 = pack2(ka.z), k3 = pack2(ka.w);
            u64 k4 = pack2(kb.x), k5 = pack2(kb.y), k6 = pack2(kb.z), k7 = pack2(kb.w);
            ffma2(acc[0][0], k0, q.x); ffma2(acc[0][1], k0, q.y);
            ffma2(acc[1][0], k1, q.x); ffma2(acc[1][1], k1, q.y);
            ffma2(acc[2][0], k2, q.x); ffma2(acc[2][1], k2, q.y);
            ffma2(acc[3][0], k3, q.x); ffma2(acc[3][1], k3, q.y);
            ffma2(acc[4][0], k4, q.x); ffma2(acc[4][1], k4, q.y);
            ffma2(acc[5][0], k5, q.x); ffma2(acc[5][1], k5, q.y);
            ffma2(acc[6][0], k6, q.x); ffma2(acc[6][1], k6, q.y);
            ffma2(acc[7][0], k7, q.x); ffma2(acc[7][1], k7, q.y);
        }
        #pragma unroll
        for (int g = 0; g < 8; g++) {
            ulonglong2 st; st.x = acc[g][0]; st.y = acc[g][1];
            *(ulonglong2*)&AT[(g0+g)*ATW + f0] = st;
        }
    }
    __syncthreads();

    // ---- softmax over g per f-column; scores tiny -> no max shift ----
    if (tid < ATW) {
        const int f = tid;
        const float rs = 0.14433756729740643f;   // 1/sqrt(48)
        float a0=0.f, a1=0.f, a2=0.f, a3=0.f;
        for (int g = 0; g < 128; g += 4) {
            float e0 = __expf(AT[(g+0)*ATW+f]*rs);
            float e1 = __expf(AT[(g+1)*ATW+f]*rs);
            float e2 = __expf(AT[(g+2)*ATW+f]*rs);
            float e3 = __expf(AT[(g+3)*ATW+f]*rs);
            AT[(g+0)*ATW+f] = e0; AT[(g+1)*ATW+f] = e1;
            AT[(g+2)*ATW+f] = e2; AT[(g+3)*ATW+f] = e3;
            a0 += e0; a1 += e1; a2 += e2; a3 += e3;
        }
        float e = __expf(AT[128*ATW+f]*rs);
        AT[128*ATW+f] = e;
        SIv[f] = 1.f / (a0+a1+a2+a3+e);
    }
    __syncthreads();

    // ---- AV: 12 c-tiles(4) x 33 f-tiles(4) = 396 tiles ----
    for (int idx = tid; idx < 12*33; idx += 512) {
        int ct = idx / 33, ft = idx % 33;
        int c0 = ct*4, f0 = ft*4;
        u64 acc[4][2] = {};
        #pragma unroll 3
        for (int g = 0; g < FF; g++) {
            ulonglong2 a = *(const ulonglong2*)&AT[g*ATW + f0];
            float4 xv = *(const float4*)&XT[g*XTW + c0];   // broadcast
            u64 x0 = pack2(xv.x), x1 = pack2(xv.y), x2 = pack2(xv.z), x3 = pack2(xv.w);
            ffma2(acc[0][0], x0, a.x); ffma2(acc[0][1], x0, a.y);
            ffma2(acc[1][0], x1, a.x); ffma2(acc[1][1], x1, a.y);
            ffma2(acc[2][0], x2, a.x); ffma2(acc[2][1], x2, a.y);
            ffma2(acc[3][0], x3, a.x); ffma2(acc[3][1], x3, a.y);
        }
        ulonglong2 iv = *(const ulonglong2*)&SIv[f0];
        #pragma unroll
        for (int i = 0; i < 4; i++) {
            float2 lo = unpack2(mul2(acc[i][0], iv.x));
            float2 hi = unpack2(mul2(acc[i][1], iv.y));
            float v[4] = {lo.x, lo.y, hi.x, hi.y};
            size_t ob = rbase + (size_t)(c0+i)*TFT;
            #pragma unroll
            for (int j = 0; j < 4; j++) {
                int f = f0 + j;
                if (f < FF) mic_out[ob + f] = v[j];
            }
        }
    }
}

// ===========================================================================
// Kernel 3: sliding-window ref attention; 16 t's/block, 512 threads.
// ===========================================================================
#define RFP 132
#define RT 16
#define RROWS (RT + 10)

__global__ __launch_bounds__(512) void ref_attn_kernel(const float* __restrict__ x_ref)
{
    __shared__ __align__(16) float krs[RROWS*RFP];
    __shared__ __align__(16) float xrs[RROWS*RFP];

    const int tid = threadIdx.x;
    const int t0 = blockIdx.x * RT;
    const int h = blockIdx.y, b = blockIdx.z;
    const size_t base = (size_t)b*CTF + (size_t)h*TFT;

    for (int i = tid; i < RROWS*RFP; i += 512) {
        int r = i / RFP, f = i % RFP;
        int tk = t0 - 10 + r;
        bool ok = (tk >= 0) && (f < FF);
        size_t gi = base + (size_t)tk*FF + f;
        krs[i] = ok ? g_Kref[gi] : 0.f;
        xrs[i] = ok ? x_ref[gi]  : 0.f;
    }
    __syncthreads();

    const int w = tid >> 5, lane = tid & 31;
    const int t = t0 + w;
    const size_t qbase = base + (size_t)t*FF;

    float qv[5], acc[5];
    bool val[5];
    #pragma unroll
    for (int k = 0; k < 5; k++) {
        int f = lane + 32*k;
        val[k] = f < FF;
        qv[k] = val[k] ? g_Q[qbase + f] : 0.f;
        acc[k] = 0.f;
    }

    for (int j = 0; j < 11; j++) {
        int tk = t - 10 + j;
        if (tk < 0) continue;
        int r = w + j;
        float e[5]; float s = 0.f;
        float xv[5];
        #pragma unroll
        for (int k = 0; k < 5; k++) {
            int f = lane + 32*k;
            float kv = val[k] ? krs[r*RFP+f] : 0.f;
            xv[k]    = val[k] ? xrs[r*RFP+f] : 0.f;
            e[k] = val[k] ? __expf(qv[k]*kv) : 0.f;
            s += e[k];
        }
        #pragma unroll
        for (int off = 16; off; off >>= 1) s += __shfl_xor_sync(0xffffffffu, s, off);
        float inv = 1.f/s;
        #pragma unroll
        for (int k = 0; k < 5; k++)
            acc[k] += xv[k] * (e[k]*inv);
    }
    #pragma unroll
    for (int k = 0; k < 5; k++) {
        int f = lane + 32*k;
        if (val[k]) g_ref[qbase + f] = acc[k];
    }
}

// ===========================================================================
// Kernel 4: fusion 96x96 GEMM + folded BN + PReLU.
// 768 threads = 2 c-groups x (12 o-tiles(8) x 32 p-tiles(4)); each warp
// streams only half the c-rows of comb; partials reduced through smem.
// ===========================================================================
#define FUS_P 128
#define FUS_NB 404
#define SMEM_FUS ((OC*OC + 2*OC + OC*FUS_P)*4)   // 86,784 B

__global__ __launch_bounds__(768) void fusion_kernel(
    const float* __restrict__ fw, const float* __restrict__ fb,
    const float* __restrict__ gamma, const float* __restrict__ beta,
    const float* __restrict__ mean, const float* __restrict__ var,
    const float* __restrict__ prelu_a,
    const float* __restrict__ micp,
    float* __restrict__ outp)
{
    extern __shared__ float smf[];
    float* WT    = smf;             // OC*OC transposed, BN-folded
    float* bias  = WT + OC*OC;
    float* alpha = bias + OC;
    float* comb  = alpha + OC;      // OC*FUS_P (reused as reduction buffer)

    const int tid = threadIdx.x;
    const int b  = blockIdx.y;
    const int p0 = blockIdx.x * FUS_P;

    if (tid < OC) {
        float a = gamma[tid] * rsqrtf(var[tid] + 1e-5f);
        alpha[tid] = a;
        bias[tid] = (fb[tid] - mean[tid]) * a + beta[tid];
    }
    __syncthreads();
    for (int i = tid; i < OC*OC; i += 768) {
        int o = i / OC, c = i % OC;
        WT[c*OC+o] = fw[i] * alpha[o];
    }
    for (int i = tid; i < OC*FUS_P; i += 768) {
        int c = i / FUS_P, p = i % FUS_P;
        int gp = p0 + p;
        float v = 0.f;
        if (gp < TFT) {
            if (c < CC) v = micp[(size_t)b*CTF + (size_t)c*TFT + gp];
            else        v = g_ref[(size_t)b*CTF + (size_t)(c-CC)*TFT + gp];
        }
        comb[i] = v;
    }
    __syncthreads();

    const int cg = tid >= 384;           // c-group: 0 or 1
    const int r  = cg ? tid - 384 : tid;
    const int ot = r >> 5, pt = r & 31;  // 12 o-tiles(8) x 32 p-tiles(4)
    const int o0 = ot*8, pp = pt*4;
    const int gp0 = p0 + pp;
    const int cbeg = cg * 48;

    u64 acc[8][2] = {};
    #pragma unroll 4
    for (int ci = 0; ci < 48; ci++) {
        int c = cbeg + ci;
        float4 wa = *(const float4*)&WT[c*OC + o0];        // broadcast
        float4 wb = *(const float4*)&WT[c*OC + o0 + 4];
        ulonglong2 xv = *(const ulonglong2*)&comb[c*FUS_P + pp];
        u64 w0 = pack2(wa.x), w1 = pack2(wa.y), w2 = pack2(wa.z), w3 = pack2(wa.w);
        u64 w4 = pack2(wb.x), w5 = pack2(wb.y), w6 = pack2(wb.z), w7 = pack2(wb.w);
        ffma2(acc[0][0], w0, xv.x); ffma2(acc[0][1], w0, xv.y);
        ffma2(acc[1][0], w1, xv.x); ffma2(acc[1][1], w1, xv.y);
        ffma2(acc[2][0], w2, xv.x); ffma2(acc[2][1], w2, xv.y);
        ffma2(acc[3][0], w3, xv.x); ffma2(acc[3][1], w3, xv.y);
        ffma2(acc[4][0], w4, xv.x); ffma2(acc[4][1], w4, xv.y);
        ffma2(acc[5][0], w5, xv.x); ffma2(acc[5][1], w5, xv.y);
        ffma2(acc[6][0], w6, xv.x); ffma2(acc[6][1], w6, xv.y);
        ffma2(acc[7][0], w7, xv.x); ffma2(acc[7][1], w7, xv.y);
    }
    __syncthreads();    // everyone done reading comb -> reuse as reduction buf

    if (cg == 1) {
        #pragma unroll
        for (int o = 0; o < 8; o++) {
            float2 lo = unpack2(acc[o][0]), hi = unpack2(acc[o][1]);
            *(float4*)&comb[(o0+o)*FUS_P + pp] = make_float4(lo.x, lo.y, hi.x, hi.y);
        }
    }
    __syncthreads();

    if (cg == 0 && gp0 < TFT) {
        const float pa = prelu_a[0];
        size_t ob = (size_t)b*OC*TFT + gp0;
        #pragma unroll
        for (int o = 0; o < 8; o++) {
            float bs = bias[o0+o];
            float2 lo = unpack2(acc[o][0]), hi = unpack2(acc[o][1]);
            float4 part = *(const float4*)&comb[(o0+o)*FUS_P + pp];
            float4 y = make_float4(lo.x + part.x + bs, lo.y + part.y + bs,
                                   hi.x + part.z + bs, hi.y + part.w + bs);
            y.x = (y.x >= 0.f) ? y.x : pa*y.x;
            y.y = (y.y >= 0.f) ? y.y : pa*y.y;
            y.z = (y.z >= 0.f) ? y.z : pa*y.z;
            y.w = (y.w >= 0.f) ? y.w : pa*y.w;
            *(float4*)&outp[ob + (size_t)(o0+o)*TFT] = y;
        }
    }
}

// ---------------------------------------------------------------------------
extern "C" void kernel_launch(void* const* d_in, const int* in_sizes, int n_in,
                              void* d_out, int out_size)
{
    const float* x_mic = (const float*)d_in[0];
    const float* x_ref = (const float*)d_in[1];
    const float* dw1w = (const float*)d_in[2];
    const float* dw1b = (const float*)d_in[3];
    const float* pw1w = (const float*)d_in[4];
    const float* pw1b = (const float*)d_in[5];
    const float* dw2w = (const float*)d_in[6];
    const float* dw2b = (const float*)d_in[7];
    const float* pw2w = (const float*)d_in[8];
    const float* pw2b = (const float*)d_in[9];
    const float* dw3w = (const float*)d_in[10];
    const float* dw3b = (const float*)d_in[11];
    const float* pw3w = (const float*)d_in[12];
    const float* pw3b = (const float*)d_in[13];
    const float* fw   = (const float*)d_in[14];
    const float* fb   = (const float*)d_in[15];
    const float* gam  = (const float*)d_in[16];
    const float* bet  = (const float*)d_in[17];
    const float* mea  = (const float*)d_in[18];
    const float* var  = (const float*)d_in[19];
    const float* pa   = (const float*)d_in[20];

    float* outp = (float*)d_out;
    float* micp = outp + OUT_SZ;    // second tuple output region

    cudaFuncSetAttribute(pw_kernel,
                         cudaFuncAttributeMaxDynamicSharedMemorySize, SMEM_PW);
    cudaFuncSetAttribute(mic_attn_kernel,
                         cudaFuncAttributeMaxDynamicSharedMemorySize, SMEM_ATTN);
    cudaFuncSetAttribute(fusion_kernel,
                         cudaFuncAttributeMaxDynamicSharedMemorySize, SMEM_FUS);

    pw_kernel<<<dim3(PW_NB, BB, 2), 384, SMEM_PW>>>(
        x_mic, x_ref, dw1w, dw1b, pw1w, pw1b, dw2w, dw2b, pw2w, pw2b,
        dw3w, dw3b, pw3w, pw3b);
    mic_attn_kernel<<<dim3(TT, BB), 512, SMEM_ATTN>>>(x_mic, micp);
    ref_attn_kernel<<<dim3(TT/RT, CC, BB), 512>>>(x_ref);
    fusion_kernel<<<dim3(FUS_NB, BB), 768, SMEM_FUS>>>(
        fw, fb, gam, bet, mea, var, pa, micp, outp);
}

// round 9
// speedup vs baseline: 1.1315x; 1.0808x over previous
#include <cuda_runtime.h>
#include <math.h>

#define CC 48
#define TT 400
#define FF 129
#define BB 2
#define TFT 51600        // T*F
#define CTF 2476800      // C*T*F
#define BCTF 4953600     // B*C*T*F
#define OC 96
#define OUT_SZ 9907200   // B*OC*T*F

typedef unsigned long long u64;

// ---- packed f32x2 helpers (used only in fusion, where they measured fastest) ----
__device__ __forceinline__ void ffma2(u64 &d, u64 a, u64 b) {
    asm("fma.rn.f32x2 %0, %1, %2, %0;" : "+l"(d) : "l"(a), "l"(b));
}
__device__ __forceinline__ u64 pack2(float v) {
    u64 r; asm("mov.b64 %0, {%1, %2};" : "=l"(r) : "f"(v), "f"(v)); return r;
}
__device__ __forceinline__ float2 unpack2(u64 v) {
    float2 f; asm("mov.b64 {%0, %1}, %2;" : "=f"(f.x), "=f"(f.y) : "l"(v)); return f;
}

// Scratch (allowed: __device__ globals, no allocation)
__device__ __align__(16) float g_Q[BCTF];
__device__ __align__(16) float g_K[BCTF];
__device__ __align__(16) float g_Kref[BCTF];
__device__ __align__(16) float g_ref[BCTF];

// ===========================================================================
// Kernel 1 (merged): z=0 -> Q = pw1(dw1(x_mic)), K = pw2(dw2(Q))
//                    z=1 -> K_ref = pw3(dw3(x_ref))
// Exact R5 version: 4x4 float register tiles, plain FFMA, 68KB smem.
// ===========================================================================
#define PW_P 128
#define PW_NB 404        // ceil(51600/128)
#define SMEM_PW ((2*CC*CC + 2*CC + 2*CC*PW_P)*4)   // 67,968 B

__global__ __launch_bounds__(384) void pw_kernel(
    const float* __restrict__ x_mic, const float* __restrict__ x_ref,
    const float* __restrict__ dw1w, const float* __restrict__ dw1b,
    const float* __restrict__ pw1w, const float* __restrict__ pw1b,
    const float* __restrict__ dw2w, const float* __restrict__ dw2b,
    const float* __restrict__ pw2w, const float* __restrict__ pw2b,
    const float* __restrict__ dw3w, const float* __restrict__ dw3b,
    const float* __restrict__ pw3w, const float* __restrict__ pw3b)
{
    extern __shared__ float smp[];
    float* W1T = smp;                  // CC*CC
    float* W2T = W1T + CC*CC;          // CC*CC
    float* bb1 = W2T + CC*CC;          // CC
    float* bb2 = bb1 + CC;             // CC
    float* xs  = bb2 + CC;             // CC*PW_P
    float* qs  = xs + CC*PW_P;         // CC*PW_P

    const int tid = threadIdx.x;
    const int b = blockIdx.y, job = blockIdx.z;
    const int p0 = blockIdx.x * PW_P;
    const float* x   = job ? x_ref : x_mic;
    const float* w1  = job ? pw3w : pw1w;
    const float* d1w = job ? dw3w : dw1w;
    const float* p1b = job ? pw3b : pw1b;
    const float* d1b = job ? dw3b : dw1b;

    for (int i = tid; i < CC*CC; i += 384) {
        int o = i / CC, c = i % CC;
        W1T[c*CC+o] = w1[i] * d1w[c];
        if (!job) W2T[c*CC+o] = pw2w[i] * dw2w[c];
    }
    if (tid < CC) {
        float s1 = p1b[tid];
        for (int c = 0; c < CC; c++) s1 += w1[tid*CC+c] * d1b[c];
        bb1[tid] = s1;
        if (!job) {
            float s2 = pw2b[tid];
            for (int c = 0; c < CC; c++) s2 += pw2w[tid*CC+c] * dw2b[c];
            bb2[tid] = s2;
        }
    }
    for (int i = tid; i < CC*PW_P; i += 384) {
        int c = i / PW_P, p = i % PW_P;
        int gp = p0 + p;
        xs[i] = (gp < TFT) ? x[(size_t)b*CTF + (size_t)c*TFT + gp] : 0.f;
    }
    __syncthreads();

    const int ot = tid >> 5, pt = tid & 31;   // 12 o-tiles x 32 p-tiles
    const int o0 = ot*4, pp = pt*4;
    const int gp0 = p0 + pp;
    float* out1 = job ? g_Kref : g_Q;

    // stage 1
    {
        float4 a0={0,0,0,0},a1={0,0,0,0},a2={0,0,0,0},a3={0,0,0,0};
        #pragma unroll 4
        for (int c = 0; c < CC; c++) {
            float4 w  = *(const float4*)&W1T[c*CC+o0];
            float4 xv = *(const float4*)&xs[c*PW_P+pp];
            a0.x+=w.x*xv.x; a0.y+=w.x*xv.y; a0.z+=w.x*xv.z; a0.w+=w.x*xv.w;
            a1.x+=w.y*xv.x; a1.y+=w.y*xv.y; a1.z+=w.y*xv.z; a1.w+=w.y*xv.w;
            a2.x+=w.z*xv.x; a2.y+=w.z*xv.y; a2.z+=w.z*xv.z; a2.w+=w.z*xv.w;
            a3.x+=w.w*xv.x; a3.y+=w.w*xv.y; a3.z+=w.w*xv.z; a3.w+=w.w*xv.w;
        }
        float4 bv = *(const float4*)&bb1[o0];
        a0.x+=bv.x; a0.y+=bv.x; a0.z+=bv.x; a0.w+=bv.x;
        a1.x+=bv.y; a1.y+=bv.y; a1.z+=bv.y; a1.w+=bv.y;
        a2.x+=bv.z; a2.y+=bv.z; a2.z+=bv.z; a2.w+=bv.z;
        a3.x+=bv.w; a3.y+=bv.w; a3.z+=bv.w; a3.w+=bv.w;
        if (!job) {
            *(float4*)&qs[(o0+0)*PW_P+pp] = a0;
            *(float4*)&qs[(o0+1)*PW_P+pp] = a1;
            *(float4*)&qs[(o0+2)*PW_P+pp] = a2;
            *(float4*)&qs[(o0+3)*PW_P+pp] = a3;
        }
        if (gp0 < TFT) {
            size_t base = (size_t)b*CTF + gp0;
            *(float4*)&out1[base + (size_t)(o0+0)*TFT] = a0;
            *(float4*)&out1[base + (size_t)(o0+1)*TFT] = a1;
            *(float4*)&out1[base + (size_t)(o0+2)*TFT] = a2;
            *(float4*)&out1[base + (size_t)(o0+3)*TFT] = a3;
        }
    }
    if (job) return;
    __syncthreads();

    // stage 2: K from Q tile in smem
    {
        float4 a0={0,0,0,0},a1={0,0,0,0},a2={0,0,0,0},a3={0,0,0,0};
        #pragma unroll 4
        for (int c = 0; c < CC; c++) {
            float4 w  = *(const float4*)&W2T[c*CC+o0];
            float4 xv = *(const float4*)&qs[c*PW_P+pp];
            a0.x+=w.x*xv.x; a0.y+=w.x*xv.y; a0.z+=w.x*xv.z; a0.w+=w.x*xv.w;
            a1.x+=w.y*xv.x; a1.y+=w.y*xv.y; a1.z+=w.y*xv.z; a1.w+=w.y*xv.w;
            a2.x+=w.z*xv.x; a2.y+=w.z*xv.y; a2.z+=w.z*xv.z; a2.w+=w.z*xv.w;
            a3.x+=w.w*xv.x; a3.y+=w.w*xv.y; a3.z+=w.w*xv.z; a3.w+=w.w*xv.w;
        }
        float4 bv = *(const float4*)&bb2[o0];
        a0.x+=bv.x; a0.y+=bv.x; a0.z+=bv.x; a0.w+=bv.x;
        a1.x+=bv.y; a1.y+=bv.y; a1.z+=bv.y; a1.w+=bv.y;
        a2.x+=bv.z; a2.y+=bv.z; a2.z+=bv.z; a2.w+=bv.z;
        a3.x+=bv.w; a3.y+=bv.w; a3.z+=bv.w; a3.w+=bv.w;
        if (gp0 < TFT) {
            size_t base = (size_t)b*CTF + gp0;
            *(float4*)&g_K[base + (size_t)(o0+0)*TFT] = a0;
            *(float4*)&g_K[base + (size_t)(o0+1)*TFT] = a1;
            *(float4*)&g_K[base + (size_t)(o0+2)*TFT] = a2;
            *(float4*)&g_K[base + (size_t)(o0+3)*TFT] = a3;
        }
    }
}

// ===========================================================================
// Kernel 2: mic attention per (b,t). Exact R5 version (288 threads,
// conflict-free transposed layouts, plain FFMA, no-shuffle softmax).
// ===========================================================================
#define ATW 132          // A_T row stride (f), mult of 4
#define KSW 136          // Ks row stride / padded g rows, mult of 8
#define XTW 52           // X_T row stride (c)
#define SMEM_ATTN ((CC*ATW + CC*KSW + KSW*XTW + KSW*ATW + ATW)*4)  // 152,080 B

__global__ __launch_bounds__(288) void mic_attn_kernel(
    const float* __restrict__ x_mic, float* __restrict__ mic_out)
{
    extern __shared__ float sm[];
    float* Qs  = sm;                   // [CC][ATW]
    float* Ks  = Qs + CC*ATW;          // [CC][KSW]
    float* XT  = Ks + CC*KSW;          // [KSW][XTW]  (X transposed)
    float* AT  = XT + KSW*XTW;         // [KSW][ATW]  (A transposed: [g][f])
    float* SIv = AT + KSW*ATW;         // [ATW] 1/sum per f

    const int tid = threadIdx.x;
    const int t = blockIdx.x, b = blockIdx.y;
    const size_t rbase = (size_t)b*CTF + (size_t)t*FF;

    for (int i = tid; i < CC*ATW; i += 288) {
        int c = i / ATW, f = i % ATW;
        Qs[i] = (f < FF) ? g_Q[rbase + (size_t)c*TFT + f] : 0.f;
    }
    for (int i = tid; i < CC*KSW; i += 288) {
        int c = i / KSW, g = i % KSW;
        Ks[i] = (g < FF) ? g_K[rbase + (size_t)c*TFT + g] : 0.f;
    }
    for (int i = tid; i < CC*KSW; i += 288) {
        int c = i / KSW, g = i % KSW;
        XT[g*XTW + c] = (g < FF) ? x_mic[rbase + (size_t)c*TFT + g] : 0.f;
    }
    __syncthreads();

    // ---- scores: 17 g-tiles(8) x 33 f-tiles(4) = 561 tiles, write A_T raw ----
    for (int idx = tid; idx < 17*33; idx += 288) {
        int gt = idx / 33, ft = idx % 33;   // lanes vary ft -> f contiguous
        int g0 = gt*8, f0 = ft*4;
        float4 s0={0,0,0,0},s1={0,0,0,0},s2={0,0,0,0},s3={0,0,0,0};
        float4 s4={0,0,0,0},s5={0,0,0,0},s6={0,0,0,0},s7={0,0,0,0};
        #pragma unroll 4
        for (int c = 0; c < CC; c++) {
            float4 q  = *(const float4*)&Qs[c*ATW + f0];
            float4 k0 = *(const float4*)&Ks[c*KSW + g0];
            float4 k1 = *(const float4*)&Ks[c*KSW + g0 + 4];
            s0.x+=k0.x*q.x; s0.y+=k0.x*q.y; s0.z+=k0.x*q.z; s0.w+=k0.x*q.w;
            s1.x+=k0.y*q.x; s1.y+=k0.y*q.y; s1.z+=k0.y*q.z; s1.w+=k0.y*q.w;
            s2.x+=k0.z*q.x; s2.y+=k0.z*q.y; s2.z+=k0.z*q.z; s2.w+=k0.z*q.w;
            s3.x+=k0.w*q.x; s3.y+=k0.w*q.y; s3.z+=k0.w*q.z; s3.w+=k0.w*q.w;
            s4.x+=k1.x*q.x; s4.y+=k1.x*q.y; s4.z+=k1.x*q.z; s4.w+=k1.x*q.w;
            s5.x+=k1.y*q.x; s5.y+=k1.y*q.y; s5.z+=k1.y*q.z; s5.w+=k1.y*q.w;
            s6.x+=k1.z*q.x; s6.y+=k1.z*q.y; s6.z+=k1.z*q.z; s6.w+=k1.z*q.w;
            s7.x+=k1.w*q.x; s7.y+=k1.w*q.y; s7.z+=k1.w*q.z; s7.w+=k1.w*q.w;
        }
        *(float4*)&AT[(g0+0)*ATW + f0] = s0;
        *(float4*)&AT[(g0+1)*ATW + f0] = s1;
        *(float4*)&AT[(g0+2)*ATW + f0] = s2;
        *(float4*)&AT[(g0+3)*ATW + f0] = s3;
        *(float4*)&AT[(g0+4)*ATW + f0] = s4;
        *(float4*)&AT[(g0+5)*ATW + f0] = s5;
        *(float4*)&AT[(g0+6)*ATW + f0] = s6;
        *(float4*)&AT[(g0+7)*ATW + f0] = s7;
    }
    __syncthreads();

    // ---- softmax over g per f-column; scores tiny -> no max shift needed ----
    if (tid < ATW) {
        const int f = tid;
        const float rs = 0.14433756729740643f;   // 1/sqrt(48)
        float a0=0.f, a1=0.f, a2=0.f, a3=0.f;
        for (int g = 0; g < 128; g += 4) {
            float e0 = __expf(AT[(g+0)*ATW+f]*rs);
            float e1 = __expf(AT[(g+1)*ATW+f]*rs);
            float e2 = __expf(AT[(g+2)*ATW+f]*rs);
            float e3 = __expf(AT[(g+3)*ATW+f]*rs);
            AT[(g+0)*ATW+f] = e0; AT[(g+1)*ATW+f] = e1;
            AT[(g+2)*ATW+f] = e2; AT[(g+3)*ATW+f] = e3;
            a0 += e0; a1 += e1; a2 += e2; a3 += e3;
        }
        float e = __expf(AT[128*ATW+f]*rs);
        AT[128*ATW+f] = e;
        SIv[f] = 1.f / (a0+a1+a2+a3+e);
    }
    __syncthreads();

    // ---- AV: 12 c-tiles x 33 f-tiles, outer product over g<129 ----
    for (int idx = tid; idx < 12*33; idx += 288) {
        int ct = idx / 33, ft = idx % 33;   // lanes vary ft
        int c0 = ct*4, f0 = ft*4;
        float4 a0={0,0,0,0},a1={0,0,0,0},a2={0,0,0,0},a3={0,0,0,0};
        #pragma unroll 3
        for (int g = 0; g < FF; g++) {
            float4 a  = *(const float4*)&AT[g*ATW + f0];
            float4 xv = *(const float4*)&XT[g*XTW + c0];
            a0.x+=xv.x*a.x; a0.y+=xv.x*a.y; a0.z+=xv.x*a.z; a0.w+=xv.x*a.w;
            a1.x+=xv.y*a.x; a1.y+=xv.y*a.y; a1.z+=xv.y*a.z; a1.w+=xv.y*a.w;
            a2.x+=xv.z*a.x; a2.y+=xv.z*a.y; a2.z+=xv.z*a.z; a2.w+=xv.z*a.w;
            a3.x+=xv.w*a.x; a3.y+=xv.w*a.y; a3.z+=xv.w*a.z; a3.w+=xv.w*a.w;
        }
        float4 iv = *(const float4*)&SIv[f0];
        float v[4][4] = {
            {a0.x*iv.x, a0.y*iv.y, a0.z*iv.z, a0.w*iv.w},
            {a1.x*iv.x, a1.y*iv.y, a1.z*iv.z, a1.w*iv.w},
            {a2.x*iv.x, a2.y*iv.y, a2.z*iv.z, a2.w*iv.w},
            {a3.x*iv.x, a3.y*iv.y, a3.z*iv.z, a3.w*iv.w}};
        #pragma unroll
        for (int i = 0; i < 4; i++) {
            size_t ob = rbase + (size_t)(c0+i)*TFT;
            #pragma unroll
            for (int j = 0; j < 4; j++) {
                int f = f0 + j;
                if (f < FF) mic_out[ob + f] = v[i][j];
            }
        }
    }
}

// ===========================================================================
// Kernel 3: sliding-window ref attention. Exact R5 version (8 t's, 256 thr).
// ===========================================================================
#define RFP 132

__global__ __launch_bounds__(256) void ref_attn_kernel(const float* __restrict__ x_ref)
{
    __shared__ __align__(16) float krs[18*RFP];
    __shared__ __align__(16) float xrs[18*RFP];

    const int tid = threadIdx.x;
    const int t0 = blockIdx.x * 8;
    const int h = blockIdx.y, b = blockIdx.z;
    const size_t base = (size_t)b*CTF + (size_t)h*TFT;

    for (int i = tid; i < 18*RFP; i += 256) {
        int r = i / RFP, f = i % RFP;
        int tk = t0 - 10 + r;
        bool ok = (tk >= 0) && (f < FF);
        size_t gi = base + (size_t)tk*FF + f;
        krs[i] = ok ? g_Kref[gi] : 0.f;
        xrs[i] = ok ? x_ref[gi]  : 0.f;
    }
    __syncthreads();

    const int w = tid >> 5, lane = tid & 31;
    const int t = t0 + w;
    const size_t qbase = base + (size_t)t*FF;

    float qv[5], acc[5];
    bool val[5];
    #pragma unroll
    for (int k = 0; k < 5; k++) {
        int f = lane + 32*k;
        val[k] = f < FF;
        qv[k] = val[k] ? g_Q[qbase + f] : 0.f;
        acc[k] = 0.f;
    }

    for (int j = 0; j < 11; j++) {
        int tk = t - 10 + j;
        if (tk < 0) continue;
        int r = w + j;
        float e[5]; float s = 0.f;
        float xv[5];
        #pragma unroll
        for (int k = 0; k < 5; k++) {
            int f = lane + 32*k;
            float kv = val[k] ? krs[r*RFP+f] : 0.f;
            xv[k]    = val[k] ? xrs[r*RFP+f] : 0.f;
            e[k] = val[k] ? __expf(qv[k]*kv) : 0.f;
            s += e[k];
        }
        #pragma unroll
        for (int off = 16; off; off >>= 1) s += __shfl_xor_sync(0xffffffffu, s, off);
        float inv = 1.f/s;
        #pragma unroll
        for (int k = 0; k < 5; k++)
            acc[k] += xv[k] * (e[k]*inv);
    }
    #pragma unroll
    for (int k = 0; k < 5; k++) {
        int f = lane + 32*k;
        if (val[k]) g_ref[qbase + f] = acc[k];
    }
}

// ===========================================================================
// Kernel 4: fusion. Exact R6 version (measured 101 µs): 768 threads,
// 4o x 4p FFMA2+pack2, 40 regs, 2 CTAs/SM.
// ===========================================================================
#define FUS_P 128
#define FUS_NB 404
#define SMEM_FUS ((OC*OC + 2*OC + OC*FUS_P)*4)   // 86,784 B

__global__ __launch_bounds__(768) void fusion_kernel(
    const float* __restrict__ fw, const float* __restrict__ fb,
    const float* __restrict__ gamma, const float* __restrict__ beta,
    const float* __restrict__ mean, const float* __restrict__ var,
    const float* __restrict__ prelu_a,
    const float* __restrict__ micp,
    float* __restrict__ outp)
{
    extern __shared__ float smf[];
    float* WT    = smf;             // OC*OC transposed, BN-folded
    float* bias  = WT + OC*OC;
    float* alpha = bias + OC;
    float* comb  = alpha + OC;      // OC*FUS_P

    const int tid = threadIdx.x;
    const int b  = blockIdx.y;
    const int p0 = blockIdx.x * FUS_P;

    if (tid < OC) {
        float a = gamma[tid] * rsqrtf(var[tid] + 1e-5f);
        alpha[tid] = a;
        bias[tid] = (fb[tid] - mean[tid]) * a + beta[tid];
    }
    __syncthreads();
    for (int i = tid; i < OC*OC; i += 768) {
        int o = i / OC, c = i % OC;
        WT[c*OC+o] = fw[i] * alpha[o];
    }
    for (int i = tid; i < OC*FUS_P; i += 768) {
        int c = i / FUS_P, p = i % FUS_P;
        int gp = p0 + p;
        float v = 0.f;
        if (gp < TFT) {
            if (c < CC) v = micp[(size_t)b*CTF + (size_t)c*TFT + gp];
            else        v = g_ref[(size_t)b*CTF + (size_t)(c-CC)*TFT + gp];
        }
        comb[i] = v;
    }
    __syncthreads();

    const float pa = prelu_a[0];
    const int ot = tid >> 5, pt = tid & 31;    // 24 o-tiles(4) x 32 p-tiles(4)
    const int o0 = ot*4, pp = pt*4;
    const int gp0 = p0 + pp;

    u64 acc[4][2] = {};
    #pragma unroll 4
    for (int c = 0; c < OC; c++) {
        float4 w = *(const float4*)&WT[c*OC + o0];           // broadcast
        ulonglong2 xv = *(const ulonglong2*)&comb[c*FUS_P + pp];
        u64 w0 = pack2(w.x), w1 = pack2(w.y), w2 = pack2(w.z), w3 = pack2(w.w);
        ffma2(acc[0][0], w0, xv.x); ffma2(acc[0][1], w0, xv.y);
        ffma2(acc[1][0], w1, xv.x); ffma2(acc[1][1], w1, xv.y);
        ffma2(acc[2][0], w2, xv.x); ffma2(acc[2][1], w2, xv.y);
        ffma2(acc[3][0], w3, xv.x); ffma2(acc[3][1], w3, xv.y);
    }
    if (gp0 < TFT) {
        size_t ob = (size_t)b*OC*TFT + gp0;
        #pragma unroll
        for (int o = 0; o < 4; o++) {
            float bs = bias[o0+o];
            float2 lo = unpack2(acc[o][0]), hi = unpack2(acc[o][1]);
            float4 y = make_float4(lo.x+bs, lo.y+bs, hi.x+bs, hi.y+bs);
            y.x = (y.x >= 0.f) ? y.x : pa*y.x;
            y.y = (y.y >= 0.f) ? y.y : pa*y.y;
            y.z = (y.z >= 0.f) ? y.z : pa*y.z;
            y.w = (y.w >= 0.f) ? y.w : pa*y.w;
            *(float4*)&outp[ob + (size_t)(o0+o)*TFT] = y;
        }
    }
}

// ---------------------------------------------------------------------------
extern "C" void kernel_launch(void* const* d_in, const int* in_sizes, int n_in,
                              void* d_out, int out_size)
{
    const float* x_mic = (const float*)d_in[0];
    const float* x_ref = (const float*)d_in[1];
    const float* dw1w = (const float*)d_in[2];
    const float* dw1b = (const float*)d_in[3];
    const float* pw1w = (const float*)d_in[4];
    const float* pw1b = (const float*)d_in[5];
    const float* dw2w = (const float*)d_in[6];
    const float* dw2b = (const float*)d_in[7];
    const float* pw2w = (const float*)d_in[8];
    const float* pw2b = (const float*)d_in[9];
    const float* dw3w = (const float*)d_in[10];
    const float* dw3b = (const float*)d_in[11];
    const float* pw3w = (const float*)d_in[12];
    const float* pw3b = (const float*)d_in[13];
    const float* fw   = (const float*)d_in[14];
    const float* fb   = (const float*)d_in[15];
    const float* gam  = (const float*)d_in[16];
    const float* bet  = (const float*)d_in[17];
    const float* mea  = (const float*)d_in[18];
    const float* var  = (const float*)d_in[19];
    const float* pa   = (const float*)d_in[20];

    float* outp = (float*)d_out;
    float* micp = outp + OUT_SZ;    // second tuple output region

    cudaFuncSetAttribute(pw_kernel,
                         cudaFuncAttributeMaxDynamicSharedMemorySize, SMEM_PW);
    cudaFuncSetAttribute(mic_attn_kernel,
                         cudaFuncAttributeMaxDynamicSharedMemorySize, SMEM_ATTN);
    cudaFuncSetAttribute(fusion_kernel,
                         cudaFuncAttributeMaxDynamicSharedMemorySize, SMEM_FUS);

    pw_kernel<<<dim3(PW_NB, BB, 2), 384, SMEM_PW>>>(
        x_mic, x_ref, dw1w, dw1b, pw1w, pw1b, dw2w, dw2b, pw2w, pw2b,
        dw3w, dw3b, pw3w, pw3b);
    mic_attn_kernel<<<dim3(TT, BB), 288, SMEM_ATTN>>>(x_mic, micp);
    ref_attn_kernel<<<dim3(TT/8, CC, BB), 256>>>(x_ref);
    fusion_kernel<<<dim3(FUS_NB, BB), 768, SMEM_FUS>>>(
        fw, fb, gam, bet, mea, var, pa, micp, outp);
}

// round 10
// speedup vs baseline: 1.1710x; 1.0349x over previous
#include <cuda_runtime.h>
#include <math.h>

#define CC 48
#define TT 400
#define FF 129
#define BB 2
#define TFT 51600        // T*F
#define CTF 2476800      // C*T*F
#define BCTF 4953600     // B*C*T*F
#define OC 96
#define OUT_SZ 9907200   // B*OC*T*F

typedef unsigned long long u64;

// ---- packed f32x2 helpers (used only in fusion, where they measured fastest) ----
__device__ __forceinline__ void ffma2(u64 &d, u64 a, u64 b) {
    asm("fma.rn.f32x2 %0, %1, %2, %0;" : "+l"(d) : "l"(a), "l"(b));
}
__device__ __forceinline__ u64 pack2(float v) {
    u64 r; asm("mov.b64 %0, {%1, %2};" : "=l"(r) : "f"(v), "f"(v)); return r;
}
__device__ __forceinline__ float2 unpack2(u64 v) {
    float2 f; asm("mov.b64 {%0, %1}, %2;" : "=f"(f.x), "=f"(f.y) : "l"(v)); return f;
}

// Scratch (allowed: __device__ globals, no allocation)
__device__ __align__(16) float g_Q[BCTF];
__device__ __align__(16) float g_K[BCTF];
__device__ __align__(16) float g_Kref[BCTF];
__device__ __align__(16) float g_ref[BCTF];

// ===========================================================================
// Kernel 1 (merged): z=0 -> Q = pw1(dw1(x_mic)), K = pw2(dw2(Q))
//                    z=1 -> K_ref = pw3(dw3(x_ref))
// Exact R5 version: 4x4 float register tiles, plain FFMA, 68KB smem.
// ===========================================================================
#define PW_P 128
#define PW_NB 404        // ceil(51600/128)
#define SMEM_PW ((2*CC*CC + 2*CC + 2*CC*PW_P)*4)   // 67,968 B

__global__ __launch_bounds__(384) void pw_kernel(
    const float* __restrict__ x_mic, const float* __restrict__ x_ref,
    const float* __restrict__ dw1w, const float* __restrict__ dw1b,
    const float* __restrict__ pw1w, const float* __restrict__ pw1b,
    const float* __restrict__ dw2w, const float* __restrict__ dw2b,
    const float* __restrict__ pw2w, const float* __restrict__ pw2b,
    const float* __restrict__ dw3w, const float* __restrict__ dw3b,
    const float* __restrict__ pw3w, const float* __restrict__ pw3b)
{
    extern __shared__ float smp[];
    float* W1T = smp;                  // CC*CC
    float* W2T = W1T + CC*CC;          // CC*CC
    float* bb1 = W2T + CC*CC;          // CC
    float* bb2 = bb1 + CC;             // CC
    float* xs  = bb2 + CC;             // CC*PW_P
    float* qs  = xs + CC*PW_P;         // CC*PW_P

    const int tid = threadIdx.x;
    const int b = blockIdx.y, job = blockIdx.z;
    const int p0 = blockIdx.x * PW_P;
    const float* x   = job ? x_ref : x_mic;
    const float* w1  = job ? pw3w : pw1w;
    const float* d1w = job ? dw3w : dw1w;
    const float* p1b = job ? pw3b : pw1b;
    const float* d1b = job ? dw3b : dw1b;

    for (int i = tid; i < CC*CC; i += 384) {
        int o = i / CC, c = i % CC;
        W1T[c*CC+o] = w1[i] * d1w[c];
        if (!job) W2T[c*CC+o] = pw2w[i] * dw2w[c];
    }
    if (tid < CC) {
        float s1 = p1b[tid];
        for (int c = 0; c < CC; c++) s1 += w1[tid*CC+c] * d1b[c];
        bb1[tid] = s1;
        if (!job) {
            float s2 = pw2b[tid];
            for (int c = 0; c < CC; c++) s2 += pw2w[tid*CC+c] * dw2b[c];
            bb2[tid] = s2;
        }
    }
    for (int i = tid; i < CC*PW_P; i += 384) {
        int c = i / PW_P, p = i % PW_P;
        int gp = p0 + p;
        xs[i] = (gp < TFT) ? x[(size_t)b*CTF + (size_t)c*TFT + gp] : 0.f;
    }
    __syncthreads();

    const int ot = tid >> 5, pt = tid & 31;   // 12 o-tiles x 32 p-tiles
    const int o0 = ot*4, pp = pt*4;
    const int gp0 = p0 + pp;
    float* out1 = job ? g_Kref : g_Q;

    // stage 1
    {
        float4 a0={0,0,0,0},a1={0,0,0,0},a2={0,0,0,0},a3={0,0,0,0};
        #pragma unroll 4
        for (int c = 0; c < CC; c++) {
            float4 w  = *(const float4*)&W1T[c*CC+o0];
            float4 xv = *(const float4*)&xs[c*PW_P+pp];
            a0.x+=w.x*xv.x; a0.y+=w.x*xv.y; a0.z+=w.x*xv.z; a0.w+=w.x*xv.w;
            a1.x+=w.y*xv.x; a1.y+=w.y*xv.y; a1.z+=w.y*xv.z; a1.w+=w.y*xv.w;
            a2.x+=w.z*xv.x; a2.y+=w.z*xv.y; a2.z+=w.z*xv.z; a2.w+=w.z*xv.w;
            a3.x+=w.w*xv.x; a3.y+=w.w*xv.y; a3.z+=w.w*xv.z; a3.w+=w.w*xv.w;
        }
        float4 bv = *(const float4*)&bb1[o0];
        a0.x+=bv.x; a0.y+=bv.x; a0.z+=bv.x; a0.w+=bv.x;
        a1.x+=bv.y; a1.y+=bv.y; a1.z+=bv.y; a1.w+=bv.y;
        a2.x+=bv.z; a2.y+=bv.z; a2.z+=bv.z; a2.w+=bv.z;
        a3.x+=bv.w; a3.y+=bv.w; a3.z+=bv.w; a3.w+=bv.w;
        if (!job) {
            *(float4*)&qs[(o0+0)*PW_P+pp] = a0;
            *(float4*)&qs[(o0+1)*PW_P+pp] = a1;
            *(float4*)&qs[(o0+2)*PW_P+pp] = a2;
            *(float4*)&qs[(o0+3)*PW_P+pp] = a3;
        }
        if (gp0 < TFT) {
            size_t base = (size_t)b*CTF + gp0;
            *(float4*)&out1[base + (size_t)(o0+0)*TFT] = a0;
            *(float4*)&out1[base + (size_t)(o0+1)*TFT] = a1;
            *(float4*)&out1[base + (size_t)(o0+2)*TFT] = a2;
            *(float4*)&out1[base + (size_t)(o0+3)*TFT] = a3;
        }
    }
    if (job) return;
    __syncthreads();

    // stage 2: K from Q tile in smem
    {
        float4 a0={0,0,0,0},a1={0,0,0,0},a2={0,0,0,0},a3={0,0,0,0};
        #pragma unroll 4
        for (int c = 0; c < CC; c++) {
            float4 w  = *(const float4*)&W2T[c*CC+o0];
            float4 xv = *(const float4*)&qs[c*PW_P+pp];
            a0.x+=w.x*xv.x; a0.y+=w.x*xv.y; a0.z+=w.x*xv.z; a0.w+=w.x*xv.w;
            a1.x+=w.y*xv.x; a1.y+=w.y*xv.y; a1.z+=w.y*xv.z; a1.w+=w.y*xv.w;
            a2.x+=w.z*xv.x; a2.y+=w.z*xv.y; a2.z+=w.z*xv.z; a2.w+=w.z*xv.w;
            a3.x+=w.w*xv.x; a3.y+=w.w*xv.y; a3.z+=w.w*xv.z; a3.w+=w.w*xv.w;
        }
        float4 bv = *(const float4*)&bb2[o0];
        a0.x+=bv.x; a0.y+=bv.x; a0.z+=bv.x; a0.w+=bv.x;
        a1.x+=bv.y; a1.y+=bv.y; a1.z+=bv.y; a1.w+=bv.y;
        a2.x+=bv.z; a2.y+=bv.z; a2.z+=bv.z; a2.w+=bv.z;
        a3.x+=bv.w; a3.y+=bv.w; a3.z+=bv.w; a3.w+=bv.w;
        if (gp0 < TFT) {
            size_t base = (size_t)b*CTF + gp0;
            *(float4*)&g_K[base + (size_t)(o0+0)*TFT] = a0;
            *(float4*)&g_K[base + (size_t)(o0+1)*TFT] = a1;
            *(float4*)&g_K[base + (size_t)(o0+2)*TFT] = a2;
            *(float4*)&g_K[base + (size_t)(o0+3)*TFT] = a3;
        }
    }
}

// ===========================================================================
// Kernel 2: mic attention, f-SPLIT: each CTA handles a 68-wide f-chunk
// (2 chunks per (b,t)). Softmax is per-f-column over g, so the split is
// exact. smem 104.7KB -> 2 CTAs/SM (was 152KB -> 1), 18 warps/SM.
// ===========================================================================
#define FHW 68           // f-chunk width (2*68 >= 129), mult of 4
#define KSW 136          // K row stride / padded g rows, mult of 8
#define XTW 52           // X_T row stride (c)
#define SMEM_ATTN ((CC*FHW + CC*KSW + KSW*XTW + KSW*FHW + FHW)*4)  // 104,720 B

__global__ __launch_bounds__(288) void mic_attn_kernel(
    const float* __restrict__ x_mic, float* __restrict__ mic_out)
{
    extern __shared__ float sm[];
    float* Qs  = sm;                   // [CC][FHW]   (this chunk's Q columns)
    float* Ks  = Qs + CC*FHW;          // [CC][KSW]   (full g)
    float* XT  = Ks + CC*KSW;          // [KSW][XTW]  (X transposed, full g)
    float* AT  = XT + KSW*XTW;         // [KSW][FHW]  (scores^T: [g][f_local])
    float* SIv = AT + KSW*FHW;         // [FHW] 1/sum per f_local

    const int tid = threadIdx.x;
    const int t = blockIdx.x, half = blockIdx.y, b = blockIdx.z;
    const int fbase = half * FHW;
    const size_t rbase = (size_t)b*CTF + (size_t)t*FF;

    for (int i = tid; i < CC*FHW; i += 288) {
        int c = i / FHW, fl = i % FHW;
        int f = fbase + fl;
        Qs[i] = (f < FF) ? g_Q[rbase + (size_t)c*TFT + f] : 0.f;
    }
    for (int i = tid; i < CC*KSW; i += 288) {
        int c = i / KSW, g = i % KSW;
        Ks[i] = (g < FF) ? g_K[rbase + (size_t)c*TFT + g] : 0.f;
    }
    for (int i = tid; i < CC*KSW; i += 288) {
        int c = i / KSW, g = i % KSW;
        XT[g*XTW + c] = (g < FF) ? x_mic[rbase + (size_t)c*TFT + g] : 0.f;
    }
    __syncthreads();

    // ---- scores: 17 g-tiles(8) x 17 f-tiles(4) = 289 tiles over 288 thr ----
    for (int idx = tid; idx < 17*17; idx += 288) {
        int gt = idx / 17, ft = idx % 17;
        int g0 = gt*8, f0 = ft*4;
        float4 s0={0,0,0,0},s1={0,0,0,0},s2={0,0,0,0},s3={0,0,0,0};
        float4 s4={0,0,0,0},s5={0,0,0,0},s6={0,0,0,0},s7={0,0,0,0};
        #pragma unroll 4
        for (int c = 0; c < CC; c++) {
            float4 q  = *(const float4*)&Qs[c*FHW + f0];
            float4 k0 = *(const float4*)&Ks[c*KSW + g0];
            float4 k1 = *(const float4*)&Ks[c*KSW + g0 + 4];
            s0.x+=k0.x*q.x; s0.y+=k0.x*q.y; s0.z+=k0.x*q.z; s0.w+=k0.x*q.w;
            s1.x+=k0.y*q.x; s1.y+=k0.y*q.y; s1.z+=k0.y*q.z; s1.w+=k0.y*q.w;
            s2.x+=k0.z*q.x; s2.y+=k0.z*q.y; s2.z+=k0.z*q.z; s2.w+=k0.z*q.w;
            s3.x+=k0.w*q.x; s3.y+=k0.w*q.y; s3.z+=k0.w*q.z; s3.w+=k0.w*q.w;
            s4.x+=k1.x*q.x; s4.y+=k1.x*q.y; s4.z+=k1.x*q.z; s4.w+=k1.x*q.w;
            s5.x+=k1.y*q.x; s5.y+=k1.y*q.y; s5.z+=k1.y*q.z; s5.w+=k1.y*q.w;
            s6.x+=k1.z*q.x; s6.y+=k1.z*q.y; s6.z+=k1.z*q.z; s6.w+=k1.z*q.w;
            s7.x+=k1.w*q.x; s7.y+=k1.w*q.y; s7.z+=k1.w*q.z; s7.w+=k1.w*q.w;
        }
        *(float4*)&AT[(g0+0)*FHW + f0] = s0;
        *(float4*)&AT[(g0+1)*FHW + f0] = s1;
        *(float4*)&AT[(g0+2)*FHW + f0] = s2;
        *(float4*)&AT[(g0+3)*FHW + f0] = s3;
        *(float4*)&AT[(g0+4)*FHW + f0] = s4;
        *(float4*)&AT[(g0+5)*FHW + f0] = s5;
        *(float4*)&AT[(g0+6)*FHW + f0] = s6;
        *(float4*)&AT[(g0+7)*FHW + f0] = s7;
    }
    __syncthreads();

    // ---- softmax over g per f-column; scores tiny -> no max shift needed ----
    if (tid < FHW) {
        const int f = tid;
        const float rs = 0.14433756729740643f;   // 1/sqrt(48)
        float a0=0.f, a1=0.f, a2=0.f, a3=0.f;
        for (int g = 0; g < 128; g += 4) {
            float e0 = __expf(AT[(g+0)*FHW+f]*rs);
            float e1 = __expf(AT[(g+1)*FHW+f]*rs);
            float e2 = __expf(AT[(g+2)*FHW+f]*rs);
            float e3 = __expf(AT[(g+3)*FHW+f]*rs);
            AT[(g+0)*FHW+f] = e0; AT[(g+1)*FHW+f] = e1;
            AT[(g+2)*FHW+f] = e2; AT[(g+3)*FHW+f] = e3;
            a0 += e0; a1 += e1; a2 += e2; a3 += e3;
        }
        float e = __expf(AT[128*FHW+f]*rs);
        AT[128*FHW+f] = e;
        SIv[f] = 1.f / (a0+a1+a2+a3+e);
    }
    __syncthreads();

    // ---- AV: 12 c-tiles(4) x 17 f-tiles(4) = 204 tiles ----
    for (int idx = tid; idx < 12*17; idx += 288) {
        int ct = idx / 17, ft = idx % 17;
        int c0 = ct*4, f0 = ft*4;
        float4 a0={0,0,0,0},a1={0,0,0,0},a2={0,0,0,0},a3={0,0,0,0};
        #pragma unroll 3
        for (int g = 0; g < FF; g++) {
            float4 a  = *(const float4*)&AT[g*FHW + f0];
            float4 xv = *(const float4*)&XT[g*XTW + c0];
            a0.x+=xv.x*a.x; a0.y+=xv.x*a.y; a0.z+=xv.x*a.z; a0.w+=xv.x*a.w;
            a1.x+=xv.y*a.x; a1.y+=xv.y*a.y; a1.z+=xv.y*a.z; a1.w+=xv.y*a.w;
            a2.x+=xv.z*a.x; a2.y+=xv.z*a.y; a2.z+=xv.z*a.z; a2.w+=xv.z*a.w;
            a3.x+=xv.w*a.x; a3.y+=xv.w*a.y; a3.z+=xv.w*a.z; a3.w+=xv.w*a.w;
        }
        float4 iv = *(const float4*)&SIv[f0];
        float v[4][4] = {
            {a0.x*iv.x, a0.y*iv.y, a0.z*iv.z, a0.w*iv.w},
            {a1.x*iv.x, a1.y*iv.y, a1.z*iv.z, a1.w*iv.w},
            {a2.x*iv.x, a2.y*iv.y, a2.z*iv.z, a2.w*iv.w},
            {a3.x*iv.x, a3.y*iv.y, a3.z*iv.z, a3.w*iv.w}};
        #pragma unroll
        for (int i = 0; i < 4; i++) {
            size_t ob = rbase + (size_t)(c0+i)*TFT;
            #pragma unroll
            for (int j = 0; j < 4; j++) {
                int f = fbase + f0 + j;
                if (f < FF) mic_out[ob + f] = v[i][j];
            }
        }
    }
}

// ===========================================================================
// Kernel 3: sliding-window ref attention. Exact R5 version (8 t's, 256 thr).
// ===========================================================================
#define RFP 132

__global__ __launch_bounds__(256) void ref_attn_kernel(const float* __restrict__ x_ref)
{
    __shared__ __align__(16) float krs[18*RFP];
    __shared__ __align__(16) float xrs[18*RFP];

    const int tid = threadIdx.x;
    const int t0 = blockIdx.x * 8;
    const int h = blockIdx.y, b = blockIdx.z;
    const size_t base = (size_t)b*CTF + (size_t)h*TFT;

    for (int i = tid; i < 18*RFP; i += 256) {
        int r = i / RFP, f = i % RFP;
        int tk = t0 - 10 + r;
        bool ok = (tk >= 0) && (f < FF);
        size_t gi = base + (size_t)tk*FF + f;
        krs[i] = ok ? g_Kref[gi] : 0.f;
        xrs[i] = ok ? x_ref[gi]  : 0.f;
    }
    __syncthreads();

    const int w = tid >> 5, lane = tid & 31;
    const int t = t0 + w;
    const size_t qbase = base + (size_t)t*FF;

    float qv[5], acc[5];
    bool val[5];
    #pragma unroll
    for (int k = 0; k < 5; k++) {
        int f = lane + 32*k;
        val[k] = f < FF;
        qv[k] = val[k] ? g_Q[qbase + f] : 0.f;
        acc[k] = 0.f;
    }

    for (int j = 0; j < 11; j++) {
        int tk = t - 10 + j;
        if (tk < 0) continue;
        int r = w + j;
        float e[5]; float s = 0.f;
        float xv[5];
        #pragma unroll
        for (int k = 0; k < 5; k++) {
            int f = lane + 32*k;
            float kv = val[k] ? krs[r*RFP+f] : 0.f;
            xv[k]    = val[k] ? xrs[r*RFP+f] : 0.f;
            e[k] = val[k] ? __expf(qv[k]*kv) : 0.f;
            s += e[k];
        }
        #pragma unroll
        for (int off = 16; off; off >>= 1) s += __shfl_xor_sync(0xffffffffu, s, off);
        float inv = 1.f/s;
        #pragma unroll
        for (int k = 0; k < 5; k++)
            acc[k] += xv[k] * (e[k]*inv);
    }
    #pragma unroll
    for (int k = 0; k < 5; k++) {
        int f = lane + 32*k;
        if (val[k]) g_ref[qbase + f] = acc[k];
    }
}

// ===========================================================================
// Kernel 4: fusion. Exact R6 version (measured 101 µs): 768 threads,
// 4o x 4p FFMA2+pack2, 40 regs, 2 CTAs/SM.
// ===========================================================================
#define FUS_P 128
#define FUS_NB 404
#define SMEM_FUS ((OC*OC + 2*OC + OC*FUS_P)*4)   // 86,784 B

__global__ __launch_bounds__(768) void fusion_kernel(
    const float* __restrict__ fw, const float* __restrict__ fb,
    const float* __restrict__ gamma, const float* __restrict__ beta,
    const float* __restrict__ mean, const float* __restrict__ var,
    const float* __restrict__ prelu_a,
    const float* __restrict__ micp,
    float* __restrict__ outp)
{
    extern __shared__ float smf[];
    float* WT    = smf;             // OC*OC transposed, BN-folded
    float* bias  = WT + OC*OC;
    float* alpha = bias + OC;
    float* comb  = alpha + OC;      // OC*FUS_P

    const int tid = threadIdx.x;
    const int b  = blockIdx.y;
    const int p0 = blockIdx.x * FUS_P;

    if (tid < OC) {
        float a = gamma[tid] * rsqrtf(var[tid] + 1e-5f);
        alpha[tid] = a;
        bias[tid] = (fb[tid] - mean[tid]) * a + beta[tid];
    }
    __syncthreads();
    for (int i = tid; i < OC*OC; i += 768) {
        int o = i / OC, c = i % OC;
        WT[c*OC+o] = fw[i] * alpha[o];
    }
    for (int i = tid; i < OC*FUS_P; i += 768) {
        int c = i / FUS_P, p = i % FUS_P;
        int gp = p0 + p;
        float v = 0.f;
        if (gp < TFT) {
            if (c < CC) v = micp[(size_t)b*CTF + (size_t)c*TFT + gp];
            else        v = g_ref[(size_t)b*CTF + (size_t)(c-CC)*TFT + gp];
        }
        comb[i] = v;
    }
    __syncthreads();

    const float pa = prelu_a[0];
    const int ot = tid >> 5, pt = tid & 31;    // 24 o-tiles(4) x 32 p-tiles(4)
    const int o0 = ot*4, pp = pt*4;
    const int gp0 = p0 + pp;

    u64 acc[4][2] = {};
    #pragma unroll 4
    for (int c = 0; c < OC; c++) {
        float4 w = *(const float4*)&WT[c*OC + o0];           // broadcast
        ulonglong2 xv = *(const ulonglong2*)&comb[c*FUS_P + pp];
        u64 w0 = pack2(w.x), w1 = pack2(w.y), w2 = pack2(w.z), w3 = pack2(w.w);
        ffma2(acc[0][0], w0, xv.x); ffma2(acc[0][1], w0, xv.y);
        ffma2(acc[1][0], w1, xv.x); ffma2(acc[1][1], w1, xv.y);
        ffma2(acc[2][0], w2, xv.x); ffma2(acc[2][1], w2, xv.y);
        ffma2(acc[3][0], w3, xv.x); ffma2(acc[3][1], w3, xv.y);
    }
    if (gp0 < TFT) {
        size_t ob = (size_t)b*OC*TFT + gp0;
        #pragma unroll
        for (int o = 0; o < 4; o++) {
            float bs = bias[o0+o];
            float2 lo = unpack2(acc[o][0]), hi = unpack2(acc[o][1]);
            float4 y = make_float4(lo.x+bs, lo.y+bs, hi.x+bs, hi.y+bs);
            y.x = (y.x >= 0.f) ? y.x : pa*y.x;
            y.y = (y.y >= 0.f) ? y.y : pa*y.y;
            y.z = (y.z >= 0.f) ? y.z : pa*y.z;
            y.w = (y.w >= 0.f) ? y.w : pa*y.w;
            *(float4*)&outp[ob + (size_t)(o0+o)*TFT] = y;
        }
    }
}

// ---------------------------------------------------------------------------
extern "C" void kernel_launch(void* const* d_in, const int* in_sizes, int n_in,
                              void* d_out, int out_size)
{
    const float* x_mic = (const float*)d_in[0];
    const float* x_ref = (const float*)d_in[1];
    const float* dw1w = (const float*)d_in[2];
    const float* dw1b = (const float*)d_in[3];
    const float* pw1w = (const float*)d_in[4];
    const float* pw1b = (const float*)d_in[5];
    const float* dw2w = (const float*)d_in[6];
    const float* dw2b = (const float*)d_in[7];
    const float* pw2w = (const float*)d_in[8];
    const float* pw2b = (const float*)d_in[9];
    const float* dw3w = (const float*)d_in[10];
    const float* dw3b = (const float*)d_in[11];
    const float* pw3w = (const float*)d_in[12];
    const float* pw3b = (const float*)d_in[13];
    const float* fw   = (const float*)d_in[14];
    const float* fb   = (const float*)d_in[15];
    const float* gam  = (const float*)d_in[16];
    const float* bet  = (const float*)d_in[17];
    const float* mea  = (const float*)d_in[18];
    const float* var  = (const float*)d_in[19];
    const float* pa   = (const float*)d_in[20];

    float* outp = (float*)d_out;
    float* micp = outp + OUT_SZ;    // second tuple output region

    cudaFuncSetAttribute(pw_kernel,
                         cudaFuncAttributeMaxDynamicSharedMemorySize, SMEM_PW);
    cudaFuncSetAttribute(mic_attn_kernel,
                         cudaFuncAttributeMaxDynamicSharedMemorySize, SMEM_ATTN);
    cudaFuncSetAttribute(fusion_kernel,
                         cudaFuncAttributeMaxDynamicSharedMemorySize, SMEM_FUS);

    pw_kernel<<<dim3(PW_NB, BB, 2), 384, SMEM_PW>>>(
        x_mic, x_ref, dw1w, dw1b, pw1w, pw1b, dw2w, dw2b, pw2w, pw2b,
        dw3w, dw3b, pw3w, pw3b);
    mic_attn_kernel<<<dim3(TT, 2, BB), 288, SMEM_ATTN>>>(x_mic, micp);
    ref_attn_kernel<<<dim3(TT/8, CC, BB), 256>>>(x_ref);
    fusion_kernel<<<dim3(FUS_NB, BB), 768, SMEM_FUS>>>(
        fw, fb, gam, bet, mea, var, pa, micp, outp);
}

// round 12
// speedup vs baseline: 1.1740x; 1.0026x over previous
#include <cuda_runtime.h>
#include <math.h>

#define CC 48
#define TT 400
#define FF 129
#define BB 2
#define TFT 51600        // T*F
#define CTF 2476800      // C*T*F
#define BCTF 4953600     // B*C*T*F
#define OC 96
#define OUT_SZ 9907200   // B*OC*T*F

typedef unsigned long long u64;

// ---- packed f32x2 helpers (fusion only) ----
__device__ __forceinline__ void ffma2(u64 &d, u64 a, u64 b) {
    asm("fma.rn.f32x2 %0, %1, %2, %0;" : "+l"(d) : "l"(a), "l"(b));
}
__device__ __forceinline__ u64 pack2(float v) {
    u64 r; asm("mov.b64 %0, {%1, %2};" : "=l"(r) : "f"(v), "f"(v)); return r;
}
__device__ __forceinline__ float2 unpack2(u64 v) {
    float2 f; asm("mov.b64 {%0, %1}, %2;" : "=f"(f.x), "=f"(f.y) : "l"(v)); return f;
}

// ---- tf32 helpers ----
// cvt.*.tf32.f32 requires a b32 destination; reinterpret back to float
// (tf32 bit pattern is a valid fp32 with truncated mantissa).
__device__ __forceinline__ float tf32r(float x) {
    unsigned y; asm("cvt.rna.tf32.f32 %0, %1;" : "=r"(y) : "f"(x));
    return __uint_as_float(y);
}
__device__ __forceinline__ void mma_tf32(
    float &c0, float &c1, float &c2, float &c3,
    unsigned a0, unsigned a1, unsigned a2, unsigned a3,
    unsigned b0, unsigned b1)
{
    asm("mma.sync.aligned.m16n8k8.row.col.f32.tf32.tf32.f32 "
        "{%0,%1,%2,%3}, {%4,%5,%6,%7}, {%8,%9}, {%0,%1,%2,%3};"
        : "+f"(c0), "+f"(c1), "+f"(c2), "+f"(c3)
        : "r"(a0), "r"(a1), "r"(a2), "r"(a3), "r"(b0), "r"(b1));
}

// Scratch
__device__ __align__(16) float g_Q[BCTF];
__device__ __align__(16) float g_K[BCTF];
__device__ __align__(16) float g_Kref[BCTF];
__device__ __align__(16) float g_ref[BCTF];

// ===========================================================================
// Kernel 1: pw (exact R10 version)
// ===========================================================================
#define PW_P 128
#define PW_NB 404
#define SMEM_PW ((2*CC*CC + 2*CC + 2*CC*PW_P)*4)   // 67,968 B

__global__ __launch_bounds__(384) void pw_kernel(
    const float* __restrict__ x_mic, const float* __restrict__ x_ref,
    const float* __restrict__ dw1w, const float* __restrict__ dw1b,
    const float* __restrict__ pw1w, const float* __restrict__ pw1b,
    const float* __restrict__ dw2w, const float* __restrict__ dw2b,
    const float* __restrict__ pw2w, const float* __restrict__ pw2b,
    const float* __restrict__ dw3w, const float* __restrict__ dw3b,
    const float* __restrict__ pw3w, const float* __restrict__ pw3b)
{
    extern __shared__ float smp[];
    float* W1T = smp;
    float* W2T = W1T + CC*CC;
    float* bb1 = W2T + CC*CC;
    float* bb2 = bb1 + CC;
    float* xs  = bb2 + CC;
    float* qs  = xs + CC*PW_P;

    const int tid = threadIdx.x;
    const int b = blockIdx.y, job = blockIdx.z;
    const int p0 = blockIdx.x * PW_P;
    const float* x   = job ? x_ref : x_mic;
    const float* w1  = job ? pw3w : pw1w;
    const float* d1w = job ? dw3w : dw1w;
    const float* p1b = job ? pw3b : pw1b;
    const float* d1b = job ? dw3b : dw1b;

    for (int i = tid; i < CC*CC; i += 384) {
        int o = i / CC, c = i % CC;
        W1T[c*CC+o] = w1[i] * d1w[c];
        if (!job) W2T[c*CC+o] = pw2w[i] * dw2w[c];
    }
    if (tid < CC) {
        float s1 = p1b[tid];
        for (int c = 0; c < CC; c++) s1 += w1[tid*CC+c] * d1b[c];
        bb1[tid] = s1;
        if (!job) {
            float s2 = pw2b[tid];
            for (int c = 0; c < CC; c++) s2 += pw2w[tid*CC+c] * dw2b[c];
            bb2[tid] = s2;
        }
    }
    for (int i = tid; i < CC*PW_P; i += 384) {
        int c = i / PW_P, p = i % PW_P;
        int gp = p0 + p;
        xs[i] = (gp < TFT) ? x[(size_t)b*CTF + (size_t)c*TFT + gp] : 0.f;
    }
    __syncthreads();

    const int ot = tid >> 5, pt = tid & 31;
    const int o0 = ot*4, pp = pt*4;
    const int gp0 = p0 + pp;
    float* out1 = job ? g_Kref : g_Q;

    {
        float4 a0={0,0,0,0},a1={0,0,0,0},a2={0,0,0,0},a3={0,0,0,0};
        #pragma unroll 4
        for (int c = 0; c < CC; c++) {
            float4 w  = *(const float4*)&W1T[c*CC+o0];
            float4 xv = *(const float4*)&xs[c*PW_P+pp];
            a0.x+=w.x*xv.x; a0.y+=w.x*xv.y; a0.z+=w.x*xv.z; a0.w+=w.x*xv.w;
            a1.x+=w.y*xv.x; a1.y+=w.y*xv.y; a1.z+=w.y*xv.z; a1.w+=w.y*xv.w;
            a2.x+=w.z*xv.x; a2.y+=w.z*xv.y; a2.z+=w.z*xv.z; a2.w+=w.z*xv.w;
            a3.x+=w.w*xv.x; a3.y+=w.w*xv.y; a3.z+=w.w*xv.z; a3.w+=w.w*xv.w;
        }
        float4 bv = *(const float4*)&bb1[o0];
        a0.x+=bv.x; a0.y+=bv.x; a0.z+=bv.x; a0.w+=bv.x;
        a1.x+=bv.y; a1.y+=bv.y; a1.z+=bv.y; a1.w+=bv.y;
        a2.x+=bv.z; a2.y+=bv.z; a2.z+=bv.z; a2.w+=bv.z;
        a3.x+=bv.w; a3.y+=bv.w; a3.z+=bv.w; a3.w+=bv.w;
        if (!job) {
            *(float4*)&qs[(o0+0)*PW_P+pp] = a0;
            *(float4*)&qs[(o0+1)*PW_P+pp] = a1;
            *(float4*)&qs[(o0+2)*PW_P+pp] = a2;
            *(float4*)&qs[(o0+3)*PW_P+pp] = a3;
        }
        if (gp0 < TFT) {
            size_t base = (size_t)b*CTF + gp0;
            *(float4*)&out1[base + (size_t)(o0+0)*TFT] = a0;
            *(float4*)&out1[base + (size_t)(o0+1)*TFT] = a1;
            *(float4*)&out1[base + (size_t)(o0+2)*TFT] = a2;
            *(float4*)&out1[base + (size_t)(o0+3)*TFT] = a3;
        }
    }
    if (job) return;
    __syncthreads();

    {
        float4 a0={0,0,0,0},a1={0,0,0,0},a2={0,0,0,0},a3={0,0,0,0};
        #pragma unroll 4
        for (int c = 0; c < CC; c++) {
            float4 w  = *(const float4*)&W2T[c*CC+o0];
            float4 xv = *(const float4*)&qs[c*PW_P+pp];
            a0.x+=w.x*xv.x; a0.y+=w.x*xv.y; a0.z+=w.x*xv.z; a0.w+=w.x*xv.w;
            a1.x+=w.y*xv.x; a1.y+=w.y*xv.y; a1.z+=w.y*xv.z; a1.w+=w.y*xv.w;
            a2.x+=w.z*xv.x; a2.y+=w.z*xv.y; a2.z+=w.z*xv.z; a2.w+=w.z*xv.w;
            a3.x+=w.w*xv.x; a3.y+=w.w*xv.y; a3.z+=w.w*xv.z; a3.w+=w.w*xv.w;
        }
        float4 bv = *(const float4*)&bb2[o0];
        a0.x+=bv.x; a0.y+=bv.x; a0.z+=bv.x; a0.w+=bv.x;
        a1.x+=bv.y; a1.y+=bv.y; a1.z+=bv.y; a1.w+=bv.y;
        a2.x+=bv.z; a2.y+=bv.z; a2.z+=bv.z; a2.w+=bv.z;
        a3.x+=bv.w; a3.y+=bv.w; a3.z+=bv.w; a3.w+=bv.w;
        if (gp0 < TFT) {
            size_t base = (size_t)b*CTF + gp0;
            *(float4*)&g_K[base + (size_t)(o0+0)*TFT] = a0;
            *(float4*)&g_K[base + (size_t)(o0+1)*TFT] = a1;
            *(float4*)&g_K[base + (size_t)(o0+2)*TFT] = a2;
            *(float4*)&g_K[base + (size_t)(o0+3)*TFT] = a3;
        }
    }
}

// ===========================================================================
// Kernel 2: mic attention via tf32 mma.sync (m16n8k8). One CTA per (b,t).
//   scores: A=Q[f][c] row-major, B=K[g][c] col-major -> S[f][g]
//   softmax: thread-per-f-row over contiguous S rows; exp in place (tf32-
//            rounded so AV's mma consumes exactly the summed values)
//   AV: A=X[c][g] row-major, B=S[f][g] (col-major k=g) -> O[c][f]*SIv[f]
// ===========================================================================
#define QSTR 52          // Q/K row stride (48+4): conflict-free frag reads
#define SSTR 137         // S row stride (odd -> conflict-free row sweep)
#define XSTR 140         // X row stride (136+4)
#define SM_Q 0                       // [144][QSTR]
#define SM_K (SM_Q + 144*QSTR)       // [136][QSTR]
#define SM_X (SM_K + 136*QSTR)       // [48][XSTR]
#define SM_S (SM_X + 48*XSTR)        // [136][SSTR]
#define SM_IV (SM_S + 136*SSTR)      // [132]
#define SMEM_MMA ((SM_IV + 132)*4)   // 160,176 B

__global__ __launch_bounds__(256) void mic_attn_kernel(
    const float* __restrict__ x_mic, float* __restrict__ mic_out)
{
    extern __shared__ float sm[];
    float* Qs = sm + SM_Q;
    float* Ks = sm + SM_K;
    float* Xs = sm + SM_X;
    float* Ss = sm + SM_S;
    float* SIv = sm + SM_IV;

    const int tid = threadIdx.x;
    const int t = blockIdx.x, b = blockIdx.y;
    const size_t rbase = (size_t)b*CTF + (size_t)t*FF;

    // ---- stage Q[f][c], K[g][c], X[c][g] with tf32 rounding ----
    for (int i = tid; i < CC*144; i += 256) {
        int c = i / 144, f = i % 144;
        Qs[f*QSTR + c] = (f < FF) ? tf32r(g_Q[rbase + (size_t)c*TFT + f]) : 0.f;
    }
    for (int i = tid; i < CC*136; i += 256) {
        int c = i / 136, g = i % 136;
        Ks[g*QSTR + c] = (g < FF) ? tf32r(g_K[rbase + (size_t)c*TFT + g]) : 0.f;
    }
    for (int i = tid; i < CC*XSTR; i += 256) {
        int c = i / XSTR, g = i % XSTR;
        Xs[c*XSTR + g] = (g < FF) ? tf32r(x_mic[rbase + (size_t)c*TFT + g]) : 0.f;
    }
    __syncthreads();

    const int w = tid >> 5, lane = tid & 31;
    const int tg = lane >> 2, t4 = lane & 3;   // groupID, threadID-in-group

    // ---- scores: warp w does m-tiles {w, w+8}; 17 n-tiles; k=48 (6 steps) ----
    for (int mt = w; mt < 9; mt += 8) {
        const int m0 = mt * 16;
        unsigned a[6][4];
        #pragma unroll
        for (int kk = 0; kk < 6; kk++) {
            const float* q = &Qs[(m0 + tg)*QSTR + kk*8 + t4];
            a[kk][0] = __float_as_uint(q[0]);
            a[kk][1] = __float_as_uint(q[8*QSTR]);
            a[kk][2] = __float_as_uint(q[4]);
            a[kk][3] = __float_as_uint(q[8*QSTR + 4]);
        }
        for (int nt = 0; nt < 17; nt++) {
            const int n0 = nt * 8;
            float c0=0.f, c1=0.f, c2=0.f, c3=0.f;
            #pragma unroll
            for (int kk = 0; kk < 6; kk++) {
                const float* kp = &Ks[(n0 + tg)*QSTR + kk*8 + t4];
                unsigned b0 = __float_as_uint(kp[0]);
                unsigned b1 = __float_as_uint(kp[4]);
                mma_tf32(c0, c1, c2, c3,
                         a[kk][0], a[kk][1], a[kk][2], a[kk][3], b0, b1);
            }
            int r0 = m0 + tg, r1 = r0 + 8;
            int cc = n0 + 2*t4;
            if (r0 < FF) { Ss[r0*SSTR + cc] = c0; Ss[r0*SSTR + cc + 1] = c1; }
            if (r1 < FF) { Ss[r1*SSTR + cc] = c2; Ss[r1*SSTR + cc + 1] = c3; }
        }
    }
    __syncthreads();

    // ---- softmax over g per f-row (contiguous, conflict-free); tiny scores
    //      -> no max shift; exp stored tf32-rounded; 1/sum deferred ----
    if (tid < FF) {
        float* row = &Ss[tid*SSTR];
        const float rs = 0.14433756729740643f;   // 1/sqrt(48)
        float s0=0.f, s1=0.f, s2=0.f, s3=0.f;
        #pragma unroll 1
        for (int g = 0; g < 128; g += 4) {
            float e0 = tf32r(__expf(row[g+0]*rs));
            float e1 = tf32r(__expf(row[g+1]*rs));
            float e2 = tf32r(__expf(row[g+2]*rs));
            float e3 = tf32r(__expf(row[g+3]*rs));
            row[g+0]=e0; row[g+1]=e1; row[g+2]=e2; row[g+3]=e3;
            s0+=e0; s1+=e1; s2+=e2; s3+=e3;
        }
        float e = tf32r(__expf(row[128]*rs));
        row[128] = e;
        SIv[tid] = 1.f / (s0+s1+s2+s3+e);
    }
    __syncthreads();

    // ---- AV: 3 m-tiles (c) x 17 n-tiles (f) = 51 jobs; k=g (17 steps) ----
    for (int job = w; job < 51; job += 8) {
        const int m0 = (job / 17) * 16;
        const int n0 = (job % 17) * 8;
        float c0=0.f, c1=0.f, c2=0.f, c3=0.f;
        #pragma unroll 4
        for (int kk = 0; kk < 17; kk++) {
            const float* xp = &Xs[(m0 + tg)*XSTR + kk*8 + t4];
            unsigned a0 = __float_as_uint(xp[0]);
            unsigned a1 = __float_as_uint(xp[8*XSTR]);
            unsigned a2 = __float_as_uint(xp[4]);
            unsigned a3 = __float_as_uint(xp[8*XSTR + 4]);
            const float* pp = &Ss[(n0 + tg)*SSTR + kk*8 + t4];
            unsigned b0 = __float_as_uint(pp[0]);
            unsigned b1 = __float_as_uint(pp[4]);
            mma_tf32(c0, c1, c2, c3, a0, a1, a2, a3, b0, b1);
        }
        const int r0 = m0 + tg, r1 = r0 + 8;      // c rows (< 48 always)
        const int f0 = n0 + 2*t4;
        if (f0 < FF) {
            float iv = SIv[f0];
            mic_out[rbase + (size_t)r0*TFT + f0] = c0 * iv;
            mic_out[rbase + (size_t)r1*TFT + f0] = c2 * iv;
        }
        if (f0 + 1 < FF) {
            float iv = SIv[f0 + 1];
            mic_out[rbase + (size_t)r0*TFT + f0 + 1] = c1 * iv;
            mic_out[rbase + (size_t)r1*TFT + f0 + 1] = c3 * iv;
        }
    }
}

// ===========================================================================
// Kernel 3: ref attention (exact R10 version)
// ===========================================================================
#define RFP 132

__global__ __launch_bounds__(256) void ref_attn_kernel(const float* __restrict__ x_ref)
{
    __shared__ __align__(16) float krs[18*RFP];
    __shared__ __align__(16) float xrs[18*RFP];

    const int tid = threadIdx.x;
    const int t0 = blockIdx.x * 8;
    const int h = blockIdx.y, b = blockIdx.z;
    const size_t base = (size_t)b*CTF + (size_t)h*TFT;

    for (int i = tid; i < 18*RFP; i += 256) {
        int r = i / RFP, f = i % RFP;
        int tk = t0 - 10 + r;
        bool ok = (tk >= 0) && (f < FF);
        size_t gi = base + (size_t)tk*FF + f;
        krs[i] = ok ? g_Kref[gi] : 0.f;
        xrs[i] = ok ? x_ref[gi]  : 0.f;
    }
    __syncthreads();

    const int w = tid >> 5, lane = tid & 31;
    const int t = t0 + w;
    const size_t qbase = base + (size_t)t*FF;

    float qv[5], acc[5];
    bool val[5];
    #pragma unroll
    for (int k = 0; k < 5; k++) {
        int f = lane + 32*k;
        val[k] = f < FF;
        qv[k] = val[k] ? g_Q[qbase + f] : 0.f;
        acc[k] = 0.f;
    }

    for (int j = 0; j < 11; j++) {
        int tk = t - 10 + j;
        if (tk < 0) continue;
        int r = w + j;
        float e[5]; float s = 0.f;
        float xv[5];
        #pragma unroll
        for (int k = 0; k < 5; k++) {
            int f = lane + 32*k;
            float kv = val[k] ? krs[r*RFP+f] : 0.f;
            xv[k]    = val[k] ? xrs[r*RFP+f] : 0.f;
            e[k] = val[k] ? __expf(qv[k]*kv) : 0.f;
            s += e[k];
        }
        #pragma unroll
        for (int off = 16; off; off >>= 1) s += __shfl_xor_sync(0xffffffffu, s, off);
        float inv = 1.f/s;
        #pragma unroll
        for (int k = 0; k < 5; k++)
            acc[k] += xv[k] * (e[k]*inv);
    }
    #pragma unroll
    for (int k = 0; k < 5; k++) {
        int f = lane + 32*k;
        if (val[k]) g_ref[qbase + f] = acc[k];
    }
}

// ===========================================================================
// Kernel 4: fusion (exact R6/R10 version, measured 101 µs)
// ===========================================================================
#define FUS_P 128
#define FUS_NB 404
#define SMEM_FUS ((OC*OC + 2*OC + OC*FUS_P)*4)   // 86,784 B

__global__ __launch_bounds__(768) void fusion_kernel(
    const float* __restrict__ fw, const float* __restrict__ fb,
    const float* __restrict__ gamma, const float* __restrict__ beta,
    const float* __restrict__ mean, const float* __restrict__ var,
    const float* __restrict__ prelu_a,
    const float* __restrict__ micp,
    float* __restrict__ outp)
{
    extern __shared__ float smf[];
    float* WT    = smf;
    float* bias  = WT + OC*OC;
    float* alpha = bias + OC;
    float* comb  = alpha + OC;

    const int tid = threadIdx.x;
    const int b  = blockIdx.y;
    const int p0 = blockIdx.x * FUS_P;

    if (tid < OC) {
        float a = gamma[tid] * rsqrtf(var[tid] + 1e-5f);
        alpha[tid] = a;
        bias[tid] = (fb[tid] - mean[tid]) * a + beta[tid];
    }
    __syncthreads();
    for (int i = tid; i < OC*OC; i += 768) {
        int o = i / OC, c = i % OC;
        WT[c*OC+o] = fw[i] * alpha[o];
    }
    for (int i = tid; i < OC*FUS_P; i += 768) {
        int c = i / FUS_P, p = i % FUS_P;
        int gp = p0 + p;
        float v = 0.f;
        if (gp < TFT) {
            if (c < CC) v = micp[(size_t)b*CTF + (size_t)c*TFT + gp];
            else        v = g_ref[(size_t)b*CTF + (size_t)(c-CC)*TFT + gp];
        }
        comb[i] = v;
    }
    __syncthreads();

    const float pa = prelu_a[0];
    const int ot = tid >> 5, pt = tid & 31;
    const int o0 = ot*4, pp = pt*4;
    const int gp0 = p0 + pp;

    u64 acc[4][2] = {};
    #pragma unroll 4
    for (int c = 0; c < OC; c++) {
        float4 w = *(const float4*)&WT[c*OC + o0];
        ulonglong2 xv = *(const ulonglong2*)&comb[c*FUS_P + pp];
        u64 w0 = pack2(w.x), w1 = pack2(w.y), w2 = pack2(w.z), w3 = pack2(w.w);
        ffma2(acc[0][0], w0, xv.x); ffma2(acc[0][1], w0, xv.y);
        ffma2(acc[1][0], w1, xv.x); ffma2(acc[1][1], w1, xv.y);
        ffma2(acc[2][0], w2, xv.x); ffma2(acc[2][1], w2, xv.y);
        ffma2(acc[3][0], w3, xv.x); ffma2(acc[3][1], w3, xv.y);
    }
    if (gp0 < TFT) {
        size_t ob = (size_t)b*OC*TFT + gp0;
        #pragma unroll
        for (int o = 0; o < 4; o++) {
            float bs = bias[o0+o];
            float2 lo = unpack2(acc[o][0]), hi = unpack2(acc[o][1]);
            float4 y = make_float4(lo.x+bs, lo.y+bs, hi.x+bs, hi.y+bs);
            y.x = (y.x >= 0.f) ? y.x : pa*y.x;
            y.y = (y.y >= 0.f) ? y.y : pa*y.y;
            y.z = (y.z >= 0.f) ? y.z : pa*y.z;
            y.w = (y.w >= 0.f) ? y.w : pa*y.w;
            *(float4*)&outp[ob + (size_t)(o0+o)*TFT] = y;
        }
    }
}

// ---------------------------------------------------------------------------
extern "C" void kernel_launch(void* const* d_in, const int* in_sizes, int n_in,
                              void* d_out, int out_size)
{
    const float* x_mic = (const float*)d_in[0];
    const float* x_ref = (const float*)d_in[1];
    const float* dw1w = (const float*)d_in[2];
    const float* dw1b = (const float*)d_in[3];
    const float* pw1w = (const float*)d_in[4];
    const float* pw1b = (const float*)d_in[5];
    const float* dw2w = (const float*)d_in[6];
    const float* dw2b = (const float*)d_in[7];
    const float* pw2w = (const float*)d_in[8];
    const float* pw2b = (const float*)d_in[9];
    const float* dw3w = (const float*)d_in[10];
    const float* dw3b = (const float*)d_in[11];
    const float* pw3w = (const float*)d_in[12];
    const float* pw3b = (const float*)d_in[13];
    const float* fw   = (const float*)d_in[14];
    const float* fb   = (const float*)d_in[15];
    const float* gam  = (const float*)d_in[16];
    const float* bet  = (const float*)d_in[17];
    const float* mea  = (const float*)d_in[18];
    const float* var  = (const float*)d_in[19];
    const float* pa   = (const float*)d_in[20];

    float* outp = (float*)d_out;
    float* micp = outp + OUT_SZ;    // second tuple output region

    cudaFuncSetAttribute(pw_kernel,
                         cudaFuncAttributeMaxDynamicSharedMemorySize, SMEM_PW);
    cudaFuncSetAttribute(mic_attn_kernel,
                         cudaFuncAttributeMaxDynamicSharedMemorySize, SMEM_MMA);
    cudaFuncSetAttribute(fusion_kernel,
                         cudaFuncAttributeMaxDynamicSharedMemorySize, SMEM_FUS);

    pw_kernel<<<dim3(PW_NB, BB, 2), 384, SMEM_PW>>>(
        x_mic, x_ref, dw1w, dw1b, pw1w, pw1b, dw2w, dw2b, pw2w, pw2b,
        dw3w, dw3b, pw3w, pw3b);
    mic_attn_kernel<<<dim3(TT, BB), 256, SMEM_MMA>>>(x_mic, micp);
    ref_attn_kernel<<<dim3(TT/8, CC, BB), 256>>>(x_ref);
    fusion_kernel<<<dim3(FUS_NB, BB), 768, SMEM_FUS>>>(
        fw, fb, gam, bet, mea, var, pa, micp, outp);
}

// round 13
// speedup vs baseline: 1.1777x; 1.0031x over previous
#include <cuda_runtime.h>
#include <math.h>

#define CC 48
#define TT 400
#define FF 129
#define BB 2
#define TFT 51600        // T*F
#define CTF 2476800      // C*T*F
#define BCTF 4953600     // B*C*T*F
#define OC 96
#define OUT_SZ 9907200   // B*OC*T*F

typedef unsigned long long u64;

// ---- tf32 helpers (validated in R12: correct fragment layouts, rel_err 2.9e-4) ----
__device__ __forceinline__ float tf32r(float x) {
    unsigned y; asm("cvt.rna.tf32.f32 %0, %1;" : "=r"(y) : "f"(x));
    return __uint_as_float(y);
}
__device__ __forceinline__ void mma_tf32(
    float &c0, float &c1, float &c2, float &c3,
    unsigned a0, unsigned a1, unsigned a2, unsigned a3,
    unsigned b0, unsigned b1)
{
    asm("mma.sync.aligned.m16n8k8.row.col.f32.tf32.tf32.f32 "
        "{%0,%1,%2,%3}, {%4,%5,%6,%7}, {%8,%9}, {%0,%1,%2,%3};"
        : "+f"(c0), "+f"(c1), "+f"(c2), "+f"(c3)
        : "r"(a0), "r"(a1), "r"(a2), "r"(a3), "r"(b0), "r"(b1));
}

// Scratch
__device__ __align__(16) float g_Q[BCTF];
__device__ __align__(16) float g_K[BCTF];
__device__ __align__(16) float g_Kref[BCTF];
__device__ __align__(16) float g_ref[BCTF];

// ===========================================================================
// Kernel 1: pw (exact R10 version)
// ===========================================================================
#define PW_P 128
#define PW_NB 404
#define SMEM_PW ((2*CC*CC + 2*CC + 2*CC*PW_P)*4)   // 67,968 B

__global__ __launch_bounds__(384) void pw_kernel(
    const float* __restrict__ x_mic, const float* __restrict__ x_ref,
    const float* __restrict__ dw1w, const float* __restrict__ dw1b,
    const float* __restrict__ pw1w, const float* __restrict__ pw1b,
    const float* __restrict__ dw2w, const float* __restrict__ dw2b,
    const float* __restrict__ pw2w, const float* __restrict__ pw2b,
    const float* __restrict__ dw3w, const float* __restrict__ dw3b,
    const float* __restrict__ pw3w, const float* __restrict__ pw3b)
{
    extern __shared__ float smp[];
    float* W1T = smp;
    float* W2T = W1T + CC*CC;
    float* bb1 = W2T + CC*CC;
    float* bb2 = bb1 + CC;
    float* xs  = bb2 + CC;
    float* qs  = xs + CC*PW_P;

    const int tid = threadIdx.x;
    const int b = blockIdx.y, job = blockIdx.z;
    const int p0 = blockIdx.x * PW_P;
    const float* x   = job ? x_ref : x_mic;
    const float* w1  = job ? pw3w : pw1w;
    const float* d1w = job ? dw3w : dw1w;
    const float* p1b = job ? pw3b : pw1b;
    const float* d1b = job ? dw3b : dw1b;

    for (int i = tid; i < CC*CC; i += 384) {
        int o = i / CC, c = i % CC;
        W1T[c*CC+o] = w1[i] * d1w[c];
        if (!job) W2T[c*CC+o] = pw2w[i] * dw2w[c];
    }
    if (tid < CC) {
        float s1 = p1b[tid];
        for (int c = 0; c < CC; c++) s1 += w1[tid*CC+c] * d1b[c];
        bb1[tid] = s1;
        if (!job) {
            float s2 = pw2b[tid];
            for (int c = 0; c < CC; c++) s2 += pw2w[tid*CC+c] * dw2b[c];
            bb2[tid] = s2;
        }
    }
    for (int i = tid; i < CC*PW_P; i += 384) {
        int c = i / PW_P, p = i % PW_P;
        int gp = p0 + p;
        xs[i] = (gp < TFT) ? x[(size_t)b*CTF + (size_t)c*TFT + gp] : 0.f;
    }
    __syncthreads();

    const int ot = tid >> 5, pt = tid & 31;
    const int o0 = ot*4, pp = pt*4;
    const int gp0 = p0 + pp;
    float* out1 = job ? g_Kref : g_Q;

    {
        float4 a0={0,0,0,0},a1={0,0,0,0},a2={0,0,0,0},a3={0,0,0,0};
        #pragma unroll 4
        for (int c = 0; c < CC; c++) {
            float4 w  = *(const float4*)&W1T[c*CC+o0];
            float4 xv = *(const float4*)&xs[c*PW_P+pp];
            a0.x+=w.x*xv.x; a0.y+=w.x*xv.y; a0.z+=w.x*xv.z; a0.w+=w.x*xv.w;
            a1.x+=w.y*xv.x; a1.y+=w.y*xv.y; a1.z+=w.y*xv.z; a1.w+=w.y*xv.w;
            a2.x+=w.z*xv.x; a2.y+=w.z*xv.y; a2.z+=w.z*xv.z; a2.w+=w.z*xv.w;
            a3.x+=w.w*xv.x; a3.y+=w.w*xv.y; a3.z+=w.w*xv.z; a3.w+=w.w*xv.w;
        }
        float4 bv = *(const float4*)&bb1[o0];
        a0.x+=bv.x; a0.y+=bv.x; a0.z+=bv.x; a0.w+=bv.x;
        a1.x+=bv.y; a1.y+=bv.y; a1.z+=bv.y; a1.w+=bv.y;
        a2.x+=bv.z; a2.y+=bv.z; a2.z+=bv.z; a2.w+=bv.z;
        a3.x+=bv.w; a3.y+=bv.w; a3.z+=bv.w; a3.w+=bv.w;
        if (!job) {
            *(float4*)&qs[(o0+0)*PW_P+pp] = a0;
            *(float4*)&qs[(o0+1)*PW_P+pp] = a1;
            *(float4*)&qs[(o0+2)*PW_P+pp] = a2;
            *(float4*)&qs[(o0+3)*PW_P+pp] = a3;
        }
        if (gp0 < TFT) {
            size_t base = (size_t)b*CTF + gp0;
            *(float4*)&out1[base + (size_t)(o0+0)*TFT] = a0;
            *(float4*)&out1[base + (size_t)(o0+1)*TFT] = a1;
            *(float4*)&out1[base + (size_t)(o0+2)*TFT] = a2;
            *(float4*)&out1[base + (size_t)(o0+3)*TFT] = a3;
        }
    }
    if (job) return;
    __syncthreads();

    {
        float4 a0={0,0,0,0},a1={0,0,0,0},a2={0,0,0,0},a3={0,0,0,0};
        #pragma unroll 4
        for (int c = 0; c < CC; c++) {
            float4 w  = *(const float4*)&W2T[c*CC+o0];
            float4 xv = *(const float4*)&qs[c*PW_P+pp];
            a0.x+=w.x*xv.x; a0.y+=w.x*xv.y; a0.z+=w.x*xv.z; a0.w+=w.x*xv.w;
            a1.x+=w.y*xv.x; a1.y+=w.y*xv.y; a1.z+=w.y*xv.z; a1.w+=w.y*xv.w;
            a2.x+=w.z*xv.x; a2.y+=w.z*xv.y; a2.z+=w.z*xv.z; a2.w+=w.z*xv.w;
            a3.x+=w.w*xv.x; a3.y+=w.w*xv.y; a3.z+=w.w*xv.z; a3.w+=w.w*xv.w;
        }
        float4 bv = *(const float4*)&bb2[o0];
        a0.x+=bv.x; a0.y+=bv.x; a0.z+=bv.x; a0.w+=bv.x;
        a1.x+=bv.y; a1.y+=bv.y; a1.z+=bv.y; a1.w+=bv.y;
        a2.x+=bv.z; a2.y+=bv.z; a2.z+=bv.z; a2.w+=bv.z;
        a3.x+=bv.w; a3.y+=bv.w; a3.z+=bv.w; a3.w+=bv.w;
        if (gp0 < TFT) {
            size_t base = (size_t)b*CTF + gp0;
            *(float4*)&g_K[base + (size_t)(o0+0)*TFT] = a0;
            *(float4*)&g_K[base + (size_t)(o0+1)*TFT] = a1;
            *(float4*)&g_K[base + (size_t)(o0+2)*TFT] = a2;
            *(float4*)&g_K[base + (size_t)(o0+3)*TFT] = a3;
        }
    }
}

// ===========================================================================
// Kernel 2: mic attention via tf32 mma.sync (exact R12 version)
// ===========================================================================
#define QSTR 52
#define SSTR 137
#define XSTR 140
#define SM_Q 0
#define SM_K (SM_Q + 144*QSTR)
#define SM_X (SM_K + 136*QSTR)
#define SM_S (SM_X + 48*XSTR)
#define SM_IV (SM_S + 136*SSTR)
#define SMEM_MMA ((SM_IV + 132)*4)   // 160,176 B

__global__ __launch_bounds__(256) void mic_attn_kernel(
    const float* __restrict__ x_mic, float* __restrict__ mic_out)
{
    extern __shared__ float sm[];
    float* Qs = sm + SM_Q;
    float* Ks = sm + SM_K;
    float* Xs = sm + SM_X;
    float* Ss = sm + SM_S;
    float* SIv = sm + SM_IV;

    const int tid = threadIdx.x;
    const int t = blockIdx.x, b = blockIdx.y;
    const size_t rbase = (size_t)b*CTF + (size_t)t*FF;

    for (int i = tid; i < CC*144; i += 256) {
        int c = i / 144, f = i % 144;
        Qs[f*QSTR + c] = (f < FF) ? tf32r(g_Q[rbase + (size_t)c*TFT + f]) : 0.f;
    }
    for (int i = tid; i < CC*136; i += 256) {
        int c = i / 136, g = i % 136;
        Ks[g*QSTR + c] = (g < FF) ? tf32r(g_K[rbase + (size_t)c*TFT + g]) : 0.f;
    }
    for (int i = tid; i < CC*XSTR; i += 256) {
        int c = i / XSTR, g = i % XSTR;
        Xs[c*XSTR + g] = (g < FF) ? tf32r(x_mic[rbase + (size_t)c*TFT + g]) : 0.f;
    }
    __syncthreads();

    const int w = tid >> 5, lane = tid & 31;
    const int tg = lane >> 2, t4 = lane & 3;

    for (int mt = w; mt < 9; mt += 8) {
        const int m0 = mt * 16;
        unsigned a[6][4];
        #pragma unroll
        for (int kk = 0; kk < 6; kk++) {
            const float* q = &Qs[(m0 + tg)*QSTR + kk*8 + t4];
            a[kk][0] = __float_as_uint(q[0]);
            a[kk][1] = __float_as_uint(q[8*QSTR]);
            a[kk][2] = __float_as_uint(q[4]);
            a[kk][3] = __float_as_uint(q[8*QSTR + 4]);
        }
        for (int nt = 0; nt < 17; nt++) {
            const int n0 = nt * 8;
            float c0=0.f, c1=0.f, c2=0.f, c3=0.f;
            #pragma unroll
            for (int kk = 0; kk < 6; kk++) {
                const float* kp = &Ks[(n0 + tg)*QSTR + kk*8 + t4];
                unsigned b0 = __float_as_uint(kp[0]);
                unsigned b1 = __float_as_uint(kp[4]);
                mma_tf32(c0, c1, c2, c3,
                         a[kk][0], a[kk][1], a[kk][2], a[kk][3], b0, b1);
            }
            int r0 = m0 + tg, r1 = r0 + 8;
            int cc = n0 + 2*t4;
            if (r0 < FF) { Ss[r0*SSTR + cc] = c0; Ss[r0*SSTR + cc + 1] = c1; }
            if (r1 < FF) { Ss[r1*SSTR + cc] = c2; Ss[r1*SSTR + cc + 1] = c3; }
        }
    }
    __syncthreads();

    if (tid < FF) {
        float* row = &Ss[tid*SSTR];
        const float rs = 0.14433756729740643f;
        float s0=0.f, s1=0.f, s2=0.f, s3=0.f;
        #pragma unroll 1
        for (int g = 0; g < 128; g += 4) {
            float e0 = tf32r(__expf(row[g+0]*rs));
            float e1 = tf32r(__expf(row[g+1]*rs));
            float e2 = tf32r(__expf(row[g+2]*rs));
            float e3 = tf32r(__expf(row[g+3]*rs));
            row[g+0]=e0; row[g+1]=e1; row[g+2]=e2; row[g+3]=e3;
            s0+=e0; s1+=e1; s2+=e2; s3+=e3;
        }
        float e = tf32r(__expf(row[128]*rs));
        row[128] = e;
        SIv[tid] = 1.f / (s0+s1+s2+s3+e);
    }
    __syncthreads();

    for (int job = w; job < 51; job += 8) {
        const int m0 = (job / 17) * 16;
        const int n0 = (job % 17) * 8;
        float c0=0.f, c1=0.f, c2=0.f, c3=0.f;
        #pragma unroll 4
        for (int kk = 0; kk < 17; kk++) {
            const float* xp = &Xs[(m0 + tg)*XSTR + kk*8 + t4];
            unsigned a0 = __float_as_uint(xp[0]);
            unsigned a1 = __float_as_uint(xp[8*XSTR]);
            unsigned a2 = __float_as_uint(xp[4]);
            unsigned a3 = __float_as_uint(xp[8*XSTR + 4]);
            const float* pp = &Ss[(n0 + tg)*SSTR + kk*8 + t4];
            unsigned b0 = __float_as_uint(pp[0]);
            unsigned b1 = __float_as_uint(pp[4]);
            mma_tf32(c0, c1, c2, c3, a0, a1, a2, a3, b0, b1);
        }
        const int r0 = m0 + tg, r1 = r0 + 8;
        const int f0 = n0 + 2*t4;
        if (f0 < FF) {
            float iv = SIv[f0];
            mic_out[rbase + (size_t)r0*TFT + f0] = c0 * iv;
            mic_out[rbase + (size_t)r1*TFT + f0] = c2 * iv;
        }
        if (f0 + 1 < FF) {
            float iv = SIv[f0 + 1];
            mic_out[rbase + (size_t)r0*TFT + f0 + 1] = c1 * iv;
            mic_out[rbase + (size_t)r1*TFT + f0 + 1] = c3 * iv;
        }
    }
}

// ===========================================================================
// Kernel 3: ref attention (exact R10 version)
// ===========================================================================
#define RFP 132

__global__ __launch_bounds__(256) void ref_attn_kernel(const float* __restrict__ x_ref)
{
    __shared__ __align__(16) float krs[18*RFP];
    __shared__ __align__(16) float xrs[18*RFP];

    const int tid = threadIdx.x;
    const int t0 = blockIdx.x * 8;
    const int h = blockIdx.y, b = blockIdx.z;
    const size_t base = (size_t)b*CTF + (size_t)h*TFT;

    for (int i = tid; i < 18*RFP; i += 256) {
        int r = i / RFP, f = i % RFP;
        int tk = t0 - 10 + r;
        bool ok = (tk >= 0) && (f < FF);
        size_t gi = base + (size_t)tk*FF + f;
        krs[i] = ok ? g_Kref[gi] : 0.f;
        xrs[i] = ok ? x_ref[gi]  : 0.f;
    }
    __syncthreads();

    const int w = tid >> 5, lane = tid & 31;
    const int t = t0 + w;
    const size_t qbase = base + (size_t)t*FF;

    float qv[5], acc[5];
    bool val[5];
    #pragma unroll
    for (int k = 0; k < 5; k++) {
        int f = lane + 32*k;
        val[k] = f < FF;
        qv[k] = val[k] ? g_Q[qbase + f] : 0.f;
        acc[k] = 0.f;
    }

    for (int j = 0; j < 11; j++) {
        int tk = t - 10 + j;
        if (tk < 0) continue;
        int r = w + j;
        float e[5]; float s = 0.f;
        float xv[5];
        #pragma unroll
        for (int k = 0; k < 5; k++) {
            int f = lane + 32*k;
            float kv = val[k] ? krs[r*RFP+f] : 0.f;
            xv[k]    = val[k] ? xrs[r*RFP+f] : 0.f;
            e[k] = val[k] ? __expf(qv[k]*kv) : 0.f;
            s += e[k];
        }
        #pragma unroll
        for (int off = 16; off; off >>= 1) s += __shfl_xor_sync(0xffffffffu, s, off);
        float inv = 1.f/s;
        #pragma unroll
        for (int k = 0; k < 5; k++)
            acc[k] += xv[k] * (e[k]*inv);
    }
    #pragma unroll
    for (int k = 0; k < 5; k++) {
        int f = lane + 32*k;
        if (val[k]) g_ref[qbase + f] = acc[k];
    }
}

// ===========================================================================
// Kernel 4: fusion via tf32 mma.sync (m16n8k8): O = W(96x96) @ comb(96xP)
//   A = BN-folded W[o][c] row-major (frags cached per m-tile)
//   B = combT[p][c] (n-major, k contiguous) staged transposed in smem
//   epilogue: bias + PReLU, float2 stores
// ===========================================================================
#define FP2 128
#define FNB 404          // ceil(51600/128)
#define WRS 100          // Wd row stride (4tg+t4 -> conflict-free frags)
#define CTS 100          // combT row stride
#define FSM_W 0                      // [96][WRS]
#define FSM_C (FSM_W + OC*WRS)       // [128][CTS]
#define FSM_B (FSM_C + FP2*CTS)      // bias[96]
#define FSM_A (FSM_B + OC)           // alpha[96]
#define SMEM_FUS ((FSM_A + OC)*4)    // 90,368 B -> 2 CTAs/SM

__global__ __launch_bounds__(256) void fusion_kernel(
    const float* __restrict__ fw, const float* __restrict__ fb,
    const float* __restrict__ gamma, const float* __restrict__ beta,
    const float* __restrict__ mean, const float* __restrict__ var,
    const float* __restrict__ prelu_a,
    const float* __restrict__ micp,
    float* __restrict__ outp)
{
    extern __shared__ float smf[];
    float* Wd    = smf + FSM_W;
    float* combT = smf + FSM_C;
    float* bias  = smf + FSM_B;
    float* alpha = smf + FSM_A;

    const int tid = threadIdx.x;
    const int b  = blockIdx.y;
    const int p0 = blockIdx.x * FP2;

    if (tid < OC) {
        float a = gamma[tid] * rsqrtf(var[tid] + 1e-5f);
        alpha[tid] = a;
        bias[tid] = (fb[tid] - mean[tid]) * a + beta[tid];
    }
    __syncthreads();
    for (int i = tid; i < OC*OC; i += 256) {
        int o = i / OC, c = i % OC;
        Wd[o*WRS + c] = tf32r(fw[i] * alpha[o]);
    }
    for (int i = tid; i < OC*FP2; i += 256) {
        int c = i / FP2, p = i % FP2;
        int gp = p0 + p;
        float v = 0.f;
        if (gp < TFT) {
            if (c < CC) v = micp[(size_t)b*CTF + (size_t)c*TFT + gp];
            else        v = g_ref[(size_t)b*CTF + (size_t)(c-CC)*TFT + gp];
        }
        combT[p*CTS + c] = tf32r(v);
    }
    __syncthreads();

    const int w = tid >> 5, lane = tid & 31;
    const int tg = lane >> 2, t4 = lane & 3;
    const float pa = prelu_a[0];
    const size_t obase = (size_t)b*OC*TFT;

    for (int mb = 0; mb < 6; mb++) {
        const int m0 = mb * 16;
        unsigned a[12][4];
        #pragma unroll
        for (int kk = 0; kk < 12; kk++) {
            const float* q = &Wd[(m0 + tg)*WRS + kk*8 + t4];
            a[kk][0] = __float_as_uint(q[0]);
            a[kk][1] = __float_as_uint(q[8*WRS]);
            a[kk][2] = __float_as_uint(q[4]);
            a[kk][3] = __float_as_uint(q[8*WRS + 4]);
        }
        for (int nb = w; nb < 16; nb += 8) {
            const int n0 = nb * 8;
            float c0=0.f, c1=0.f, c2=0.f, c3=0.f;
            #pragma unroll
            for (int kk = 0; kk < 12; kk++) {
                const float* pp = &combT[(n0 + tg)*CTS + kk*8 + t4];
                unsigned b0 = __float_as_uint(pp[0]);
                unsigned b1 = __float_as_uint(pp[4]);
                mma_tf32(c0, c1, c2, c3,
                         a[kk][0], a[kk][1], a[kk][2], a[kk][3], b0, b1);
            }
            const int o0 = m0 + tg, o1 = o0 + 8;
            const int pg = p0 + n0 + 2*t4;
            if (pg < TFT) {           // pg even, TFT even -> pg+1 also valid
                float bs0 = bias[o0], bs1 = bias[o1];
                float y0 = c0 + bs0, y1 = c1 + bs0;
                float y2 = c2 + bs1, y3 = c3 + bs1;
                y0 = (y0 >= 0.f) ? y0 : pa*y0;
                y1 = (y1 >= 0.f) ? y1 : pa*y1;
                y2 = (y2 >= 0.f) ? y2 : pa*y2;
                y3 = (y3 >= 0.f) ? y3 : pa*y3;
                *(float2*)&outp[obase + (size_t)o0*TFT + pg] = make_float2(y0, y1);
                *(float2*)&outp[obase + (size_t)o1*TFT + pg] = make_float2(y2, y3);
            }
        }
    }
}

// ---------------------------------------------------------------------------
extern "C" void kernel_launch(void* const* d_in, const int* in_sizes, int n_in,
                              void* d_out, int out_size)
{
    const float* x_mic = (const float*)d_in[0];
    const float* x_ref = (const float*)d_in[1];
    const float* dw1w = (const float*)d_in[2];
    const float* dw1b = (const float*)d_in[3];
    const float* pw1w = (const float*)d_in[4];
    const float* pw1b = (const float*)d_in[5];
    const float* dw2w = (const float*)d_in[6];
    const float* dw2b = (const float*)d_in[7];
    const float* pw2w = (const float*)d_in[8];
    const float* pw2b = (const float*)d_in[9];
    const float* dw3w = (const float*)d_in[10];
    const float* dw3b = (const float*)d_in[11];
    const float* pw3w = (const float*)d_in[12];
    const float* pw3b = (const float*)d_in[13];
    const float* fw   = (const float*)d_in[14];
    const float* fb   = (const float*)d_in[15];
    const float* gam  = (const float*)d_in[16];
    const float* bet  = (const float*)d_in[17];
    const float* mea  = (const float*)d_in[18];
    const float* var  = (const float*)d_in[19];
    const float* pa   = (const float*)d_in[20];

    float* outp = (float*)d_out;
    float* micp = outp + OUT_SZ;    // second tuple output region

    cudaFuncSetAttribute(pw_kernel,
                         cudaFuncAttributeMaxDynamicSharedMemorySize, SMEM_PW);
    cudaFuncSetAttribute(mic_attn_kernel,
                         cudaFuncAttributeMaxDynamicSharedMemorySize, SMEM_MMA);
    cudaFuncSetAttribute(fusion_kernel,
                         cudaFuncAttributeMaxDynamicSharedMemorySize, SMEM_FUS);

    pw_kernel<<<dim3(PW_NB, BB, 2), 384, SMEM_PW>>>(
        x_mic, x_ref, dw1w, dw1b, pw1w, pw1b, dw2w, dw2b, pw2w, pw2b,
        dw3w, dw3b, pw3w, pw3b);
    mic_attn_kernel<<<dim3(TT, BB), 256, SMEM_MMA>>>(x_mic, micp);
    ref_attn_kernel<<<dim3(TT/8, CC, BB), 256>>>(x_ref);
    fusion_kernel<<<dim3(FNB, BB), 256, SMEM_FUS>>>(
        fw, fb, gam, bet, mea, var, pa, micp, outp);
}

// round 14
// speedup vs baseline: 1.2708x; 1.0791x over previous
#include <cuda_runtime.h>
#include <math.h>

#define CC 48
#define TT 400
#define FF 129
#define BB 2
#define TFT 51600        // T*F
#define CTF 2476800      // C*T*F
#define BCTF 4953600     // B*C*T*F
#define OC 96
#define OUT_SZ 9907200   // B*OC*T*F

typedef unsigned long long u64;

// ---- tf32 helpers (validated R12/R13: correct layouts, rel_err 2.9e-4) ----
__device__ __forceinline__ float tf32r(float x) {
    unsigned y; asm("cvt.rna.tf32.f32 %0, %1;" : "=r"(y) : "f"(x));
    return __uint_as_float(y);
}
__device__ __forceinline__ void mma_tf32(
    float &c0, float &c1, float &c2, float &c3,
    unsigned a0, unsigned a1, unsigned a2, unsigned a3,
    unsigned b0, unsigned b1)
{
    asm("mma.sync.aligned.m16n8k8.row.col.f32.tf32.tf32.f32 "
        "{%0,%1,%2,%3}, {%4,%5,%6,%7}, {%8,%9}, {%0,%1,%2,%3};"
        : "+f"(c0), "+f"(c1), "+f"(c2), "+f"(c3)
        : "r"(a0), "r"(a1), "r"(a2), "r"(a3), "r"(b0), "r"(b1));
}

// Scratch
__device__ __align__(16) float g_Q[BCTF];
__device__ __align__(16) float g_K[BCTF];
__device__ __align__(16) float g_Kref[BCTF];
__device__ __align__(16) float g_ref[BCTF];

// ===========================================================================
// Kernel 1: pw (exact R10 version)
// ===========================================================================
#define PW_P 128
#define PW_NB 404
#define SMEM_PW ((2*CC*CC + 2*CC + 2*CC*PW_P)*4)   // 67,968 B

__global__ __launch_bounds__(384) void pw_kernel(
    const float* __restrict__ x_mic, const float* __restrict__ x_ref,
    const float* __restrict__ dw1w, const float* __restrict__ dw1b,
    const float* __restrict__ pw1w, const float* __restrict__ pw1b,
    const float* __restrict__ dw2w, const float* __restrict__ dw2b,
    const float* __restrict__ pw2w, const float* __restrict__ pw2b,
    const float* __restrict__ dw3w, const float* __restrict__ dw3b,
    const float* __restrict__ pw3w, const float* __restrict__ pw3b)
{
    extern __shared__ float smp[];
    float* W1T = smp;
    float* W2T = W1T + CC*CC;
    float* bb1 = W2T + CC*CC;
    float* bb2 = bb1 + CC;
    float* xs  = bb2 + CC;
    float* qs  = xs + CC*PW_P;

    const int tid = threadIdx.x;
    const int b = blockIdx.y, job = blockIdx.z;
    const int p0 = blockIdx.x * PW_P;
    const float* x   = job ? x_ref : x_mic;
    const float* w1  = job ? pw3w : pw1w;
    const float* d1w = job ? dw3w : dw1w;
    const float* p1b = job ? pw3b : pw1b;
    const float* d1b = job ? dw3b : dw1b;

    for (int i = tid; i < CC*CC; i += 384) {
        int o = i / CC, c = i % CC;
        W1T[c*CC+o] = w1[i] * d1w[c];
        if (!job) W2T[c*CC+o] = pw2w[i] * dw2w[c];
    }
    if (tid < CC) {
        float s1 = p1b[tid];
        for (int c = 0; c < CC; c++) s1 += w1[tid*CC+c] * d1b[c];
        bb1[tid] = s1;
        if (!job) {
            float s2 = pw2b[tid];
            for (int c = 0; c < CC; c++) s2 += pw2w[tid*CC+c] * dw2b[c];
            bb2[tid] = s2;
        }
    }
    for (int i = tid; i < CC*PW_P; i += 384) {
        int c = i / PW_P, p = i % PW_P;
        int gp = p0 + p;
        xs[i] = (gp < TFT) ? x[(size_t)b*CTF + (size_t)c*TFT + gp] : 0.f;
    }
    __syncthreads();

    const int ot = tid >> 5, pt = tid & 31;
    const int o0 = ot*4, pp = pt*4;
    const int gp0 = p0 + pp;
    float* out1 = job ? g_Kref : g_Q;

    {
        float4 a0={0,0,0,0},a1={0,0,0,0},a2={0,0,0,0},a3={0,0,0,0};
        #pragma unroll 4
        for (int c = 0; c < CC; c++) {
            float4 w  = *(const float4*)&W1T[c*CC+o0];
            float4 xv = *(const float4*)&xs[c*PW_P+pp];
            a0.x+=w.x*xv.x; a0.y+=w.x*xv.y; a0.z+=w.x*xv.z; a0.w+=w.x*xv.w;
            a1.x+=w.y*xv.x; a1.y+=w.y*xv.y; a1.z+=w.y*xv.z; a1.w+=w.y*xv.w;
            a2.x+=w.z*xv.x; a2.y+=w.z*xv.y; a2.z+=w.z*xv.z; a2.w+=w.z*xv.w;
            a3.x+=w.w*xv.x; a3.y+=w.w*xv.y; a3.z+=w.w*xv.z; a3.w+=w.w*xv.w;
        }
        float4 bv = *(const float4*)&bb1[o0];
        a0.x+=bv.x; a0.y+=bv.x; a0.z+=bv.x; a0.w+=bv.x;
        a1.x+=bv.y; a1.y+=bv.y; a1.z+=bv.y; a1.w+=bv.y;
        a2.x+=bv.z; a2.y+=bv.z; a2.z+=bv.z; a2.w+=bv.z;
        a3.x+=bv.w; a3.y+=bv.w; a3.z+=bv.w; a3.w+=bv.w;
        if (!job) {
            *(float4*)&qs[(o0+0)*PW_P+pp] = a0;
            *(float4*)&qs[(o0+1)*PW_P+pp] = a1;
            *(float4*)&qs[(o0+2)*PW_P+pp] = a2;
            *(float4*)&qs[(o0+3)*PW_P+pp] = a3;
        }
        if (gp0 < TFT) {
            size_t base = (size_t)b*CTF + gp0;
            *(float4*)&out1[base + (size_t)(o0+0)*TFT] = a0;
            *(float4*)&out1[base + (size_t)(o0+1)*TFT] = a1;
            *(float4*)&out1[base + (size_t)(o0+2)*TFT] = a2;
            *(float4*)&out1[base + (size_t)(o0+3)*TFT] = a3;
        }
    }
    if (job) return;
    __syncthreads();

    {
        float4 a0={0,0,0,0},a1={0,0,0,0},a2={0,0,0,0},a3={0,0,0,0};
        #pragma unroll 4
        for (int c = 0; c < CC; c++) {
            float4 w  = *(const float4*)&W2T[c*CC+o0];
            float4 xv = *(const float4*)&qs[c*PW_P+pp];
            a0.x+=w.x*xv.x; a0.y+=w.x*xv.y; a0.z+=w.x*xv.z; a0.w+=w.x*xv.w;
            a1.x+=w.y*xv.x; a1.y+=w.y*xv.y; a1.z+=w.y*xv.z; a1.w+=w.y*xv.w;
            a2.x+=w.z*xv.x; a2.y+=w.z*xv.y; a2.z+=w.z*xv.z; a2.w+=w.z*xv.w;
            a3.x+=w.w*xv.x; a3.y+=w.w*xv.y; a3.z+=w.w*xv.z; a3.w+=w.w*xv.w;
        }
        float4 bv = *(const float4*)&bb2[o0];
        a0.x+=bv.x; a0.y+=bv.x; a0.z+=bv.x; a0.w+=bv.x;
        a1.x+=bv.y; a1.y+=bv.y; a1.z+=bv.y; a1.w+=bv.y;
        a2.x+=bv.z; a2.y+=bv.z; a2.z+=bv.z; a2.w+=bv.z;
        a3.x+=bv.w; a3.y+=bv.w; a3.z+=bv.w; a3.w+=bv.w;
        if (gp0 < TFT) {
            size_t base = (size_t)b*CTF + gp0;
            *(float4*)&g_K[base + (size_t)(o0+0)*TFT] = a0;
            *(float4*)&g_K[base + (size_t)(o0+1)*TFT] = a1;
            *(float4*)&g_K[base + (size_t)(o0+2)*TFT] = a2;
            *(float4*)&g_K[base + (size_t)(o0+3)*TFT] = a3;
        }
    }
}

// ===========================================================================
// Kernel 2: mic attention via tf32 mma.sync (exact R12 version)
// ===========================================================================
#define QSTR 52
#define SSTR 137
#define XSTR 140
#define SM_Q 0
#define SM_K (SM_Q + 144*QSTR)
#define SM_X (SM_K + 136*QSTR)
#define SM_S (SM_X + 48*XSTR)
#define SM_IV (SM_S + 136*SSTR)
#define SMEM_MMA ((SM_IV + 132)*4)   // 160,176 B

__global__ __launch_bounds__(256) void mic_attn_kernel(
    const float* __restrict__ x_mic, float* __restrict__ mic_out)
{
    extern __shared__ float sm[];
    float* Qs = sm + SM_Q;
    float* Ks = sm + SM_K;
    float* Xs = sm + SM_X;
    float* Ss = sm + SM_S;
    float* SIv = sm + SM_IV;

    const int tid = threadIdx.x;
    const int t = blockIdx.x, b = blockIdx.y;
    const size_t rbase = (size_t)b*CTF + (size_t)t*FF;

    for (int i = tid; i < CC*144; i += 256) {
        int c = i / 144, f = i % 144;
        Qs[f*QSTR + c] = (f < FF) ? tf32r(g_Q[rbase + (size_t)c*TFT + f]) : 0.f;
    }
    for (int i = tid; i < CC*136; i += 256) {
        int c = i / 136, g = i % 136;
        Ks[g*QSTR + c] = (g < FF) ? tf32r(g_K[rbase + (size_t)c*TFT + g]) : 0.f;
    }
    for (int i = tid; i < CC*XSTR; i += 256) {
        int c = i / XSTR, g = i % XSTR;
        Xs[c*XSTR + g] = (g < FF) ? tf32r(x_mic[rbase + (size_t)c*TFT + g]) : 0.f;
    }
    __syncthreads();

    const int w = tid >> 5, lane = tid & 31;
    const int tg = lane >> 2, t4 = lane & 3;

    for (int mt = w; mt < 9; mt += 8) {
        const int m0 = mt * 16;
        unsigned a[6][4];
        #pragma unroll
        for (int kk = 0; kk < 6; kk++) {
            const float* q = &Qs[(m0 + tg)*QSTR + kk*8 + t4];
            a[kk][0] = __float_as_uint(q[0]);
            a[kk][1] = __float_as_uint(q[8*QSTR]);
            a[kk][2] = __float_as_uint(q[4]);
            a[kk][3] = __float_as_uint(q[8*QSTR + 4]);
        }
        for (int nt = 0; nt < 17; nt++) {
            const int n0 = nt * 8;
            float c0=0.f, c1=0.f, c2=0.f, c3=0.f;
            #pragma unroll
            for (int kk = 0; kk < 6; kk++) {
                const float* kp = &Ks[(n0 + tg)*QSTR + kk*8 + t4];
                unsigned b0 = __float_as_uint(kp[0]);
                unsigned b1 = __float_as_uint(kp[4]);
                mma_tf32(c0, c1, c2, c3,
                         a[kk][0], a[kk][1], a[kk][2], a[kk][3], b0, b1);
            }
            int r0 = m0 + tg, r1 = r0 + 8;
            int cc = n0 + 2*t4;
            if (r0 < FF) { Ss[r0*SSTR + cc] = c0; Ss[r0*SSTR + cc + 1] = c1; }
            if (r1 < FF) { Ss[r1*SSTR + cc] = c2; Ss[r1*SSTR + cc + 1] = c3; }
        }
    }
    __syncthreads();

    if (tid < FF) {
        float* row = &Ss[tid*SSTR];
        const float rs = 0.14433756729740643f;
        float s0=0.f, s1=0.f, s2=0.f, s3=0.f;
        #pragma unroll 1
        for (int g = 0; g < 128; g += 4) {
            float e0 = tf32r(__expf(row[g+0]*rs));
            float e1 = tf32r(__expf(row[g+1]*rs));
            float e2 = tf32r(__expf(row[g+2]*rs));
            float e3 = tf32r(__expf(row[g+3]*rs));
            row[g+0]=e0; row[g+1]=e1; row[g+2]=e2; row[g+3]=e3;
            s0+=e0; s1+=e1; s2+=e2; s3+=e3;
        }
        float e = tf32r(__expf(row[128]*rs));
        row[128] = e;
        SIv[tid] = 1.f / (s0+s1+s2+s3+e);
    }
    __syncthreads();

    for (int job = w; job < 51; job += 8) {
        const int m0 = (job / 17) * 16;
        const int n0 = (job % 17) * 8;
        float c0=0.f, c1=0.f, c2=0.f, c3=0.f;
        #pragma unroll 4
        for (int kk = 0; kk < 17; kk++) {
            const float* xp = &Xs[(m0 + tg)*XSTR + kk*8 + t4];
            unsigned a0 = __float_as_uint(xp[0]);
            unsigned a1 = __float_as_uint(xp[8*XSTR]);
            unsigned a2 = __float_as_uint(xp[4]);
            unsigned a3 = __float_as_uint(xp[8*XSTR + 4]);
            const float* pp = &Ss[(n0 + tg)*SSTR + kk*8 + t4];
            unsigned b0 = __float_as_uint(pp[0]);
            unsigned b1 = __float_as_uint(pp[4]);
            mma_tf32(c0, c1, c2, c3, a0, a1, a2, a3, b0, b1);
        }
        const int r0 = m0 + tg, r1 = r0 + 8;
        const int f0 = n0 + 2*t4;
        if (f0 < FF) {
            float iv = SIv[f0];
            mic_out[rbase + (size_t)r0*TFT + f0] = c0 * iv;
            mic_out[rbase + (size_t)r1*TFT + f0] = c2 * iv;
        }
        if (f0 + 1 < FF) {
            float iv = SIv[f0 + 1];
            mic_out[rbase + (size_t)r0*TFT + f0 + 1] = c1 * iv;
            mic_out[rbase + (size_t)r1*TFT + f0 + 1] = c3 * iv;
        }
    }
}

// ===========================================================================
// Kernel 3: ref attention (exact R10 version)
// ===========================================================================
#define RFP 132

__global__ __launch_bounds__(256) void ref_attn_kernel(const float* __restrict__ x_ref)
{
    __shared__ __align__(16) float krs[18*RFP];
    __shared__ __align__(16) float xrs[18*RFP];

    const int tid = threadIdx.x;
    const int t0 = blockIdx.x * 8;
    const int h = blockIdx.y, b = blockIdx.z;
    const size_t base = (size_t)b*CTF + (size_t)h*TFT;

    for (int i = tid; i < 18*RFP; i += 256) {
        int r = i / RFP, f = i % RFP;
        int tk = t0 - 10 + r;
        bool ok = (tk >= 0) && (f < FF);
        size_t gi = base + (size_t)tk*FF + f;
        krs[i] = ok ? g_Kref[gi] : 0.f;
        xrs[i] = ok ? x_ref[gi]  : 0.f;
    }
    __syncthreads();

    const int w = tid >> 5, lane = tid & 31;
    const int t = t0 + w;
    const size_t qbase = base + (size_t)t*FF;

    float qv[5], acc[5];
    bool val[5];
    #pragma unroll
    for (int k = 0; k < 5; k++) {
        int f = lane + 32*k;
        val[k] = f < FF;
        qv[k] = val[k] ? g_Q[qbase + f] : 0.f;
        acc[k] = 0.f;
    }

    for (int j = 0; j < 11; j++) {
        int tk = t - 10 + j;
        if (tk < 0) continue;
        int r = w + j;
        float e[5]; float s = 0.f;
        float xv[5];
        #pragma unroll
        for (int k = 0; k < 5; k++) {
            int f = lane + 32*k;
            float kv = val[k] ? krs[r*RFP+f] : 0.f;
            xv[k]    = val[k] ? xrs[r*RFP+f] : 0.f;
            e[k] = val[k] ? __expf(qv[k]*kv) : 0.f;
            s += e[k];
        }
        #pragma unroll
        for (int off = 16; off; off >>= 1) s += __shfl_xor_sync(0xffffffffu, s, off);
        float inv = 1.f/s;
        #pragma unroll
        for (int k = 0; k < 5; k++)
            acc[k] += xv[k] * (e[k]*inv);
    }
    #pragma unroll
    for (int k = 0; k < 5; k++) {
        int f = lane + 32*k;
        if (val[k]) g_ref[qbase + f] = acc[k];
    }
}

// ===========================================================================
// Kernel 4: fusion via tf32 mma.sync, 512 threads (R13 was latency-bound at
// occ=23%): each warp owns ONE n-tile (B frags cached, 24 regs) and loops
// over all 6 m-tiles (A frags loaded per kk -> low regs, 2 CTAs/SM fit RF).
// ===========================================================================
#define FP2 128
#define FNB 404          // ceil(51600/128)
#define WRS 100          // Wd row stride (4tg+t4 -> conflict-free frags)
#define CTS 100          // combT row stride
#define FSM_W 0                      // [96][WRS]
#define FSM_C (FSM_W + OC*WRS)       // [128][CTS]
#define FSM_B (FSM_C + FP2*CTS)      // bias[96]
#define FSM_A (FSM_B + OC)           // alpha[96]
#define SMEM_FUS ((FSM_A + OC)*4)    // 90,368 B -> 2 CTAs/SM

__global__ __launch_bounds__(512) void fusion_kernel(
    const float* __restrict__ fw, const float* __restrict__ fb,
    const float* __restrict__ gamma, const float* __restrict__ beta,
    const float* __restrict__ mean, const float* __restrict__ var,
    const float* __restrict__ prelu_a,
    const float* __restrict__ micp,
    float* __restrict__ outp)
{
    extern __shared__ float smf[];
    float* Wd    = smf + FSM_W;
    float* combT = smf + FSM_C;
    float* bias  = smf + FSM_B;
    float* alpha = smf + FSM_A;

    const int tid = threadIdx.x;
    const int b  = blockIdx.y;
    const int p0 = blockIdx.x * FP2;

    if (tid < OC) {
        float a = gamma[tid] * rsqrtf(var[tid] + 1e-5f);
        alpha[tid] = a;
        bias[tid] = (fb[tid] - mean[tid]) * a + beta[tid];
    }
    __syncthreads();
    for (int i = tid; i < OC*OC; i += 512) {
        int o = i / OC, c = i % OC;
        Wd[o*WRS + c] = tf32r(fw[i] * alpha[o]);
    }
    for (int i = tid; i < OC*FP2; i += 512) {
        int c = i / FP2, p = i % FP2;
        int gp = p0 + p;
        float v = 0.f;
        if (gp < TFT) {
            if (c < CC) v = micp[(size_t)b*CTF + (size_t)c*TFT + gp];
            else        v = g_ref[(size_t)b*CTF + (size_t)(c-CC)*TFT + gp];
        }
        combT[p*CTS + c] = tf32r(v);
    }
    __syncthreads();

    const int w = tid >> 5, lane = tid & 31;   // 16 warps: warp = n-tile
    const int tg = lane >> 2, t4 = lane & 3;
    const float pa = prelu_a[0];
    const size_t obase = (size_t)b*OC*TFT;
    const int n0 = w * 8;

    // cache B fragments for this warp's n-tile (reused across all 6 m-tiles)
    unsigned bf[12][2];
    #pragma unroll
    for (int kk = 0; kk < 12; kk++) {
        const float* pp = &combT[(n0 + tg)*CTS + kk*8 + t4];
        bf[kk][0] = __float_as_uint(pp[0]);
        bf[kk][1] = __float_as_uint(pp[4]);
    }

    const int pg = p0 + n0 + 2*t4;
    #pragma unroll 2
    for (int mb = 0; mb < 6; mb++) {
        const int m0 = mb * 16;
        float c0=0.f, c1=0.f, c2=0.f, c3=0.f;
        #pragma unroll
        for (int kk = 0; kk < 12; kk++) {
            const float* q = &Wd[(m0 + tg)*WRS + kk*8 + t4];
            unsigned a0 = __float_as_uint(q[0]);
            unsigned a1 = __float_as_uint(q[8*WRS]);
            unsigned a2 = __float_as_uint(q[4]);
            unsigned a3 = __float_as_uint(q[8*WRS + 4]);
            mma_tf32(c0, c1, c2, c3, a0, a1, a2, a3, bf[kk][0], bf[kk][1]);
        }
        const int o0 = m0 + tg, o1 = o0 + 8;
        if (pg < TFT) {              // pg even, TFT even -> pg+1 also valid
            float bs0 = bias[o0], bs1 = bias[o1];
            float y0 = c0 + bs0, y1 = c1 + bs0;
            float y2 = c2 + bs1, y3 = c3 + bs1;
            y0 = (y0 >= 0.f) ? y0 : pa*y0;
            y1 = (y1 >= 0.f) ? y1 : pa*y1;
            y2 = (y2 >= 0.f) ? y2 : pa*y2;
            y3 = (y3 >= 0.f) ? y3 : pa*y3;
            *(float2*)&outp[obase + (size_t)o0*TFT + pg] = make_float2(y0, y1);
            *(float2*)&outp[obase + (size_t)o1*TFT + pg] = make_float2(y2, y3);
        }
    }
}

// ---------------------------------------------------------------------------
extern "C" void kernel_launch(void* const* d_in, const int* in_sizes, int n_in,
                              void* d_out, int out_size)
{
    const float* x_mic = (const float*)d_in[0];
    const float* x_ref = (const float*)d_in[1];
    const float* dw1w = (const float*)d_in[2];
    const float* dw1b = (const float*)d_in[3];
    const float* pw1w = (const float*)d_in[4];
    const float* pw1b = (const float*)d_in[5];
    const float* dw2w = (const float*)d_in[6];
    const float* dw2b = (const float*)d_in[7];
    const float* pw2w = (const float*)d_in[8];
    const float* pw2b = (const float*)d_in[9];
    const float* dw3w = (const float*)d_in[10];
    const float* dw3b = (const float*)d_in[11];
    const float* pw3w = (const float*)d_in[12];
    const float* pw3b = (const float*)d_in[13];
    const float* fw   = (const float*)d_in[14];
    const float* fb   = (const float*)d_in[15];
    const float* gam  = (const float*)d_in[16];
    const float* bet  = (const float*)d_in[17];
    const float* mea  = (const float*)d_in[18];
    const float* var  = (const float*)d_in[19];
    const float* pa   = (const float*)d_in[20];

    float* outp = (float*)d_out;
    float* micp = outp + OUT_SZ;    // second tuple output region

    cudaFuncSetAttribute(pw_kernel,
                         cudaFuncAttributeMaxDynamicSharedMemorySize, SMEM_PW);
    cudaFuncSetAttribute(mic_attn_kernel,
                         cudaFuncAttributeMaxDynamicSharedMemorySize, SMEM_MMA);
    cudaFuncSetAttribute(fusion_kernel,
                         cudaFuncAttributeMaxDynamicSharedMemorySize, SMEM_FUS);

    pw_kernel<<<dim3(PW_NB, BB, 2), 384, SMEM_PW>>>(
        x_mic, x_ref, dw1w, dw1b, pw1w, pw1b, dw2w, dw2b, pw2w, pw2b,
        dw3w, dw3b, pw3w, pw3b);
    mic_attn_kernel<<<dim3(TT, BB), 256, SMEM_MMA>>>(x_mic, micp);
    ref_attn_kernel<<<dim3(TT/8, CC, BB), 256>>>(x_ref);
    fusion_kernel<<<dim3(FNB, BB), 512, SMEM_FUS>>>(
        fw, fb, gam, bet, mea, var, pa, micp, outp);
}